// round 12
// baseline (speedup 1.0000x reference)
#include <cuda_runtime.h>
#include <cuda_bf16.h>
#include <cstdint>

#define B_ 2
#define H_ 16
#define S_ 2048
#define D_ 128
#define SCALE 0.08838834764831845f   // 1/sqrt(128)
#define NEG (-1e9f)

#define CW 72                        // chunk row stride (64 data + 8 pad) bf16
#define CH_ELEMS (128 * CW)          // elems per tile (single stage)
#define SM_BYTES (4 * CH_ELEMS * 2)  // 73728 B dynamic -> 2 CTAs/SM
#define SGW 132                      // fp32 staging row stride (floats)

// Pre-transposed V: Vt[bh][n][k] = V[bh][k][n], split into bf16 hi/lo
__device__ __align__(16) __nv_bfloat16 g_VtHi[(size_t)32 * 128 * 2048];
__device__ __align__(16) __nv_bfloat16 g_VtLo[(size_t)32 * 128 * 2048];
// per (bh, key-tile 0..15, row): (tile row max, tile row sum of exp(s-max))
__device__ __align__(16) float2 g_stats[(size_t)32 * 16 * 2048];

// ---------------------------------------------------------------------------
__device__ __forceinline__ void mma_bf16(float* d,
                                         uint32_t a0, uint32_t a1, uint32_t a2, uint32_t a3,
                                         uint32_t b0, uint32_t b1) {
    asm volatile(
        "mma.sync.aligned.m16n8k16.row.col.f32.bf16.bf16.f32 "
        "{%0,%1,%2,%3}, {%4,%5,%6,%7}, {%8,%9}, {%0,%1,%2,%3};"
        : "+f"(d[0]), "+f"(d[1]), "+f"(d[2]), "+f"(d[3])
        : "r"(a0), "r"(a1), "r"(a2), "r"(a3), "r"(b0), "r"(b1));
}

__device__ __forceinline__ void ldm_x4(uint32_t& r0, uint32_t& r1, uint32_t& r2, uint32_t& r3,
                                       uint32_t addr) {
    asm volatile("ldmatrix.sync.aligned.m8n8.x4.shared.b16 {%0,%1,%2,%3}, [%4];"
                 : "=r"(r0), "=r"(r1), "=r"(r2), "=r"(r3) : "r"(addr));
}

__device__ __forceinline__ uint32_t smem_u32(const void* p) {
    return (uint32_t)__cvta_generic_to_shared(p);
}

__device__ __forceinline__ void cp_async16(uint32_t dst, const void* src) {
    asm volatile("cp.async.cg.shared.global [%0], [%1], 16;" :: "r"(dst), "l"(src));
}
#define CP_COMMIT() asm volatile("cp.async.commit_group;" ::: "memory")
#define CP_WAIT(n)  asm volatile("cp.async.wait_group %0;" :: "n"(n) : "memory")

__device__ __forceinline__ uint32_t pack2(__nv_bfloat16 a, __nv_bfloat16 b) {
    return (uint32_t)__bfloat16_as_ushort(a) | ((uint32_t)__bfloat16_as_ushort(b) << 16);
}

__device__ __forceinline__ void store_hilo4(__nv_bfloat16* hi, __nv_bfloat16* lo,
                                            uint32_t off, float4 v) {
    __nv_bfloat16 h0 = __float2bfloat16(v.x), h1 = __float2bfloat16(v.y);
    __nv_bfloat16 h2 = __float2bfloat16(v.z), h3 = __float2bfloat16(v.w);
    __nv_bfloat16 l0 = __float2bfloat16(v.x - __bfloat162float(h0));
    __nv_bfloat16 l1 = __float2bfloat16(v.y - __bfloat162float(h1));
    __nv_bfloat16 l2 = __float2bfloat16(v.z - __bfloat162float(h2));
    __nv_bfloat16 l3 = __float2bfloat16(v.w - __bfloat162float(h3));
    uint2 hp; hp.x = pack2(h0, h1); hp.y = pack2(h2, h3);
    uint2 lp; lp.x = pack2(l0, l1); lp.y = pack2(l2, l3);
    *(uint2*)(hi + off) = hp;
    *(uint2*)(lo + off) = lp;
}

__device__ __forceinline__ float warpRedMax(float v) {
    #pragma unroll
    for (int o = 16; o > 0; o >>= 1) v = fmaxf(v, __shfl_xor_sync(0xffffffffu, v, o));
    return v;
}
__device__ __forceinline__ float warpRedSum(float v) {
    #pragma unroll
    for (int o = 16; o > 0; o >>= 1) v += __shfl_xor_sync(0xffffffffu, v, o);
    return v;
}

// MMA over one 64-wide chunk (4 ksteps), accumulators 16x4 per thread
__device__ __forceinline__ void mma_chunk(float acc[16][4],
                                          uint32_t aHi, uint32_t aLo,
                                          uint32_t bHi, uint32_t bLo) {
    #pragma unroll
    for (int ks = 0; ks < 4; ++ks) {
        const uint32_t kb = ks * 32;   // 16 bf16 = 32 bytes
        uint32_t ah0, ah1, ah2, ah3, al0, al1, al2, al3;
        ldm_x4(ah0, ah1, ah2, ah3, aHi + kb);
        ldm_x4(al0, al1, al2, al3, aLo + kb);
        #pragma unroll
        for (int nt = 0; nt < 16; nt += 2) {
            const uint32_t bo = nt * (8 * CW * 2) + kb;
            uint32_t bh0, bh1, bh2, bh3, bl0, bl1, bl2, bl3;
            ldm_x4(bh0, bh1, bh2, bh3, bHi + bo);
            ldm_x4(bl0, bl1, bl2, bl3, bLo + bo);
            mma_bf16(acc[nt],     ah0, ah1, ah2, ah3, bh0, bh1);
            mma_bf16(acc[nt],     ah0, ah1, ah2, ah3, bl0, bl1);
            mma_bf16(acc[nt],     al0, al1, al2, al3, bh0, bh1);
            mma_bf16(acc[nt + 1], ah0, ah1, ah2, ah3, bh2, bh3);
            mma_bf16(acc[nt + 1], ah0, ah1, ah2, ah3, bl2, bl3);
            mma_bf16(acc[nt + 1], al0, al1, al2, al3, bh2, bh3);
        }
    }
}

// ---------------------------------------------------------------------------
// K0: V -> Vt (transposed) bf16 hi/lo
// ---------------------------------------------------------------------------
__global__ __launch_bounds__(256) void vt_kernel(const float* __restrict__ V) {
    __shared__ float t[32][33];
    const int k0 = blockIdx.x * 32, n0 = blockIdx.y * 32, bh = blockIdx.z;
    const int tid = threadIdx.x, c = tid & 31, r0 = tid >> 5;
    const float* Vb = V + (size_t)bh * S_ * D_;
    #pragma unroll
    for (int rr = r0; rr < 32; rr += 8)
        t[rr][c] = Vb[(size_t)(k0 + rr) * D_ + n0 + c];
    __syncthreads();
    __nv_bfloat16* Hb = g_VtHi + (size_t)bh * D_ * S_;
    __nv_bfloat16* Lb = g_VtLo + (size_t)bh * D_ * S_;
    #pragma unroll
    for (int rr = r0; rr < 32; rr += 8) {
        float x = t[c][rr];
        __nv_bfloat16 h = __float2bfloat16(x);
        __nv_bfloat16 l = __float2bfloat16(x - __bfloat162float(h));
        size_t o = (size_t)(n0 + rr) * S_ + k0 + c;
        Hb[o] = h;
        Lb[o] = l;
    }
}

// ---------------------------------------------------------------------------
// K1: scores -> exp(s - tilemax) in attn scratch + per-row tile stats.
// 128x128 tile per CTA. Window CTAs: final zeros + null stats.
// ---------------------------------------------------------------------------
__global__ __launch_bounds__(256, 2) void scores_mma_kernel(
    const float* __restrict__ Q, const float* __restrict__ K,
    const int* __restrict__ mask, float* __restrict__ attn)
{
    const int bh = blockIdx.z, b = bh >> 4;
    const int i0 = blockIdx.y * 128, j0 = blockIdx.x * 128, tj = blockIdx.x;
    const int tid = threadIdx.x;

    float* attnBase = attn + ((size_t)bh * S_ + i0) * S_ + j0;

    if (j0 + 128 <= (i0 * 4) / 5) {
        // fully-window tile: final attn = 0 exactly; stats are null
        const float4 z = make_float4(0.f, 0.f, 0.f, 0.f);
        #pragma unroll
        for (int it = 0; it < 16; ++it) {
            int idx = it * 256 + tid;
            *(float4*)&attnBase[(size_t)(idx >> 5) * S_ + ((idx & 31) << 2)] = z;
        }
        if (tid < 128)
            g_stats[((size_t)(bh * 16 + tj)) * S_ + i0 + tid] = make_float2(-1e30f, 0.0f);
        return;
    }

    extern __shared__ __nv_bfloat16 sm[];
    __nv_bfloat16* Ahi = sm;
    __nv_bfloat16* Alo = sm + CH_ELEMS;
    __nv_bfloat16* Bhi = sm + 2 * CH_ELEMS;
    __nv_bfloat16* Blo = sm + 3 * CH_ELEMS;

    const float* Qb = Q + ((size_t)bh * S_ + i0) * D_;
    const float* Kb = K + ((size_t)bh * S_ + j0) * D_;

    const int lane = tid & 31, warp = tid >> 5;
    const int g = lane >> 2, c = lane & 3;
    const int m0 = warp * 16;

    float acc[16][4];
    #pragma unroll
    for (int nt = 0; nt < 16; ++nt)
        #pragma unroll
        for (int q = 0; q < 4; ++q) acc[nt][q] = 0.0f;

    const uint32_t aRowOff = ((m0 + (lane & 15)) * CW + (lane >> 4) * 8) * 2;
    const uint32_t bRowOff = ((((lane >> 4) << 3) + (lane & 7)) * CW + ((lane >> 3) & 1) * 8) * 2;
    const uint32_t aHiA = smem_u32(Ahi) + aRowOff;
    const uint32_t aLoA = smem_u32(Alo) + aRowOff;
    const uint32_t bHiA = smem_u32(Bhi) + bRowOff;
    const uint32_t bLoA = smem_u32(Blo) + bRowOff;

    #pragma unroll
    for (int ch = 0; ch < 2; ++ch) {
        if (ch) __syncthreads();            // previous MMA done reading
        const int kc = ch * 64;
        #pragma unroll
        for (int it = 0; it < 8; ++it) {
            int idx = it * 256 + tid;
            int row = idx >> 4, c4 = (idx & 15) << 2;
            store_hilo4(Ahi, Alo, row * CW + c4, *(const float4*)&Qb[(size_t)row * D_ + kc + c4]);
            store_hilo4(Bhi, Blo, row * CW + c4, *(const float4*)&Kb[(size_t)row * D_ + kc + c4]);
        }
        __syncthreads();
        mma_chunk(acc, aHiA, aLoA, bHiA, bLoA);
    }
    __syncthreads();   // all warps done reading smem; reuse as fp32 staging

    float* stg = (float*)sm;
    #pragma unroll
    for (int nt = 0; nt < 16; ++nt) {
        *(float2*)&stg[(m0 + g) * SGW + nt * 8 + 2 * c]     = make_float2(acc[nt][0], acc[nt][1]);
        *(float2*)&stg[(m0 + g + 8) * SGW + nt * 8 + 2 * c] = make_float2(acc[nt][2], acc[nt][3]);
    }
    __syncthreads();

    // scale + mask + window into staging
    const int* mB = mask + (size_t)b * S_ * S_;
    #pragma unroll
    for (int it = 0; it < 16; ++it) {
        int idx = it * 256 + tid;
        int r = idx >> 5, cc = (idx & 31) * 4;
        int i = i0 + r, thr = (i * 4) / 5, j = j0 + cc;
        int4 mv = *(const int4*)&mB[(size_t)i * S_ + j];
        float4 s = *(float4*)&stg[r * SGW + cc];
        s.x = (mv.x || (j + 0) < thr) ? NEG : s.x * SCALE;
        s.y = (mv.y || (j + 1) < thr) ? NEG : s.y * SCALE;
        s.z = (mv.z || (j + 2) < thr) ? NEG : s.z * SCALE;
        s.w = (mv.w || (j + 3) < thr) ? NEG : s.w * SCALE;
        *(float4*)&stg[r * SGW + cc] = s;
    }
    __syncthreads();

    // per-row tile stats: write exp(s - tilemax) + (max, sum)
    #pragma unroll
    for (int it = 0; it < 16; ++it) {
        int r = warp * 16 + it;
        float4 v = *(float4*)&stg[r * SGW + lane * 4];
        float mx = fmaxf(fmaxf(v.x, v.y), fmaxf(v.z, v.w));
        mx = warpRedMax(mx);
        float4 e;
        e.x = __expf(v.x - mx); e.y = __expf(v.y - mx);
        e.z = __expf(v.z - mx); e.w = __expf(v.w - mx);
        float sum = (e.x + e.y) + (e.z + e.w);
        sum = warpRedSum(sum);
        *(float4*)&attnBase[(size_t)r * S_ + lane * 4] = e;
        if (lane == 0)
            g_stats[((size_t)(bh * 16 + tj)) * S_ + i0 + r] = make_float2(mx, sum);
    }
}

// ---------------------------------------------------------------------------
// K3: merge stats; normalize-on-the-fly (write final attn) + context GEMM.
// 128x128 output per CTA; V via cp.async (single stage).
// ---------------------------------------------------------------------------
__global__ __launch_bounds__(256, 2) void context_mma_kernel(
    float* __restrict__ attn, float* __restrict__ ctx)
{
    const int i0 = blockIdx.x * 128, bh = blockIdx.y;
    const int tid = threadIdx.x;

    extern __shared__ __nv_bfloat16 sm[];
    __nv_bfloat16* Phi = sm;
    __nv_bfloat16* Plo = sm + CH_ELEMS;
    __nv_bfloat16* Vhi = sm + 2 * CH_ELEMS;
    __nv_bfloat16* Vlo = sm + 3 * CH_ELEMS;
    __shared__ float sF[16][128];    // per (key-tile, row) normalize factor

    float* Pb = attn + ((size_t)bh * S_ + i0) * S_;
    const __nv_bfloat16* VtH = g_VtHi + (size_t)bh * D_ * S_;
    const __nv_bfloat16* VtL = g_VtLo + (size_t)bh * D_ * S_;

    // merge split-softmax stats: sF[kt][row] = e^{mx_kt - M} / sum
    if (tid < 128) {
        const size_t row = (size_t)i0 + tid;
        float2 st[16];
        #pragma unroll
        for (int kt = 0; kt < 16; ++kt)
            st[kt] = g_stats[((size_t)(bh * 16 + kt)) * S_ + row];
        float M = -1e30f;
        #pragma unroll
        for (int kt = 0; kt < 16; ++kt) M = fmaxf(M, st[kt].x);
        float e[16], sum = 0.0f;
        #pragma unroll
        for (int kt = 0; kt < 16; ++kt) { e[kt] = __expf(st[kt].x - M); sum += st[kt].y * e[kt]; }
        float inv = 1.0f / sum;
        #pragma unroll
        for (int kt = 0; kt < 16; ++kt) sF[kt][tid] = e[kt] * inv;
    }

    const int lane = tid & 31, warp = tid >> 5;
    const int g = lane >> 2, c = lane & 3;
    const int m0 = warp * 16;

    float acc[16][4];
    #pragma unroll
    for (int nt = 0; nt < 16; ++nt)
        #pragma unroll
        for (int q = 0; q < 4; ++q) acc[nt][q] = 0.0f;

    const uint32_t aRowOff = ((m0 + (lane & 15)) * CW + (lane >> 4) * 8) * 2;
    const uint32_t bRowOff = ((((lane >> 4) << 3) + (lane & 7)) * CW + ((lane >> 3) & 1) * 8) * 2;
    const uint32_t aHiA = smem_u32(Phi) + aRowOff;
    const uint32_t aLoA = smem_u32(Plo) + aRowOff;
    const uint32_t bHiA = smem_u32(Vhi) + bRowOff;
    const uint32_t bLoA = smem_u32(Vlo) + bRowOff;
    const uint32_t vHiBase = smem_u32(Vhi);
    const uint32_t vLoBase = smem_u32(Vlo);

    const int vn = tid >> 3, vk8 = (tid & 7) << 3;   // cp.async: n row, k offset

    const int ch0 = (((i0 * 4) / 5) >> 7) * 2;   // first nonzero 64-chunk
    __syncthreads();   // sF ready

    for (int ch = ch0; ch < 32; ++ch) {
        if (ch > ch0) __syncthreads();          // previous MMA done reading
        const int k0g = ch * 64;
        const int kt = ch >> 1;
        // V: cp.async into single stage (overlaps the P loop below)
        #pragma unroll
        for (int it = 0; it < 4; ++it) {
            int n = vn + it * 32;
            uint32_t doff = (n * CW + vk8) * 2;
            cp_async16(vHiBase + doff, &VtH[(size_t)n * S_ + k0g + vk8]);
            cp_async16(vLoBase + doff, &VtL[(size_t)n * S_ + k0g + vk8]);
        }
        CP_COMMIT();
        // P: read exp'd values, normalize (1 FMUL), write FINAL attn, split hi/lo
        #pragma unroll
        for (int it = 0; it < 8; ++it) {
            int idx = it * 256 + tid;
            int row = idx >> 4, c4 = (idx & 15) << 2;
            float f = sF[kt][row];
            float4 v = *(const float4*)&Pb[(size_t)row * S_ + k0g + c4];
            v.x *= f; v.y *= f; v.z *= f; v.w *= f;
            *(float4*)&Pb[(size_t)row * S_ + k0g + c4] = v;   // final attn
            store_hilo4(Phi, Plo, row * CW + c4, v);
        }
        CP_WAIT(0);
        __syncthreads();
        mma_chunk(acc, aHiA, aLoA, bHiA, bLoA);
    }
    __syncthreads();   // all warps done with smem; reuse as staging

    float* stg = (float*)sm;
    #pragma unroll
    for (int nt = 0; nt < 16; ++nt) {
        *(float2*)&stg[(m0 + g) * SGW + nt * 8 + 2 * c]     = make_float2(acc[nt][0], acc[nt][1]);
        *(float2*)&stg[(m0 + g + 8) * SGW + nt * 8 + 2 * c] = make_float2(acc[nt][2], acc[nt][3]);
    }
    __syncthreads();

    #pragma unroll
    for (int it = 0; it < 16; ++it) {
        int idx = it * 256 + tid;
        int r = idx >> 5, c4 = (idx & 31) << 2;
        *(float4*)&ctx[((size_t)bh * S_ + i0 + r) * D_ + c4] = *(float4*)&stg[r * SGW + c4];
    }
}

// ---------------------------------------------------------------------------
// kernel_launch
// ---------------------------------------------------------------------------
extern "C" void kernel_launch(void* const* d_in, const int* in_sizes, int n_in,
                              void* d_out, int out_size)
{
    const float* Q    = (const float*)d_in[0];
    const float* K    = (const float*)d_in[1];
    const float* V    = (const float*)d_in[2];
    const int*   mask = (const int*)d_in[3];

    float* out  = (float*)d_out;
    float* ctx  = out;
    float* attn = out + (size_t)B_ * H_ * S_ * D_;

    static bool attrs_set = false;
    if (!attrs_set) {
        cudaFuncSetAttribute(scores_mma_kernel, cudaFuncAttributeMaxDynamicSharedMemorySize, SM_BYTES);
        cudaFuncSetAttribute(context_mma_kernel, cudaFuncAttributeMaxDynamicSharedMemorySize, SM_BYTES);
        attrs_set = true;
    }

    vt_kernel<<<dim3(S_ / 32, D_ / 32, B_ * H_), 256>>>(V);

    dim3 g1(S_ / 128, S_ / 128, B_ * H_);
    scores_mma_kernel<<<g1, 256, SM_BYTES>>>(Q, K, mask, attn);

    dim3 g3(S_ / 128, B_ * H_);
    context_mma_kernel<<<g3, 256, SM_BYTES>>>(attn, ctx);

    (void)in_sizes; (void)n_in; (void)out_size;
}

// round 13
// speedup vs baseline: 1.1538x; 1.1538x over previous
#include <cuda_runtime.h>
#include <cuda_bf16.h>
#include <cstdint>

#define B_ 2
#define H_ 16
#define S_ 2048
#define D_ 128
#define SCALE 0.08838834764831845f   // 1/sqrt(128)
#define NEG (-1e9f)

// ctx kernel chunking (unchanged from R11)
#define CW 72                        // 64 data + 8 pad (bf16 elems)
#define CH_ELEMS (128 * CW)
#define SM_BYTES_C (6 * CH_ELEMS * 2)   // P hi/lo + V hi/lo x2 stages = 110592 B

// scores kernel chunking (new: 32-wide, double-buffered, cp.async direct)
#define CWS 40                       // 32 data + 8 pad
#define CHS_ELEMS (128 * CWS)        // 5120
#define SM_BYTES_S (8 * CHS_ELEMS * 2)  // 2 stages x 4 tiles = 81920 B

#define SGW 132                      // fp32 staging row stride (floats)

// Pre-split operands in global memory (bf16 hi/lo)
__device__ __align__(16) __nv_bfloat16 g_VtHi[(size_t)32 * 128 * 2048];  // V transposed
__device__ __align__(16) __nv_bfloat16 g_VtLo[(size_t)32 * 128 * 2048];
__device__ __align__(16) __nv_bfloat16 g_QHi[(size_t)32 * 2048 * 128];   // natural layout
__device__ __align__(16) __nv_bfloat16 g_QLo[(size_t)32 * 2048 * 128];
__device__ __align__(16) __nv_bfloat16 g_KHi[(size_t)32 * 2048 * 128];
__device__ __align__(16) __nv_bfloat16 g_KLo[(size_t)32 * 2048 * 128];

// ---------------------------------------------------------------------------
__device__ __forceinline__ void mma_bf16(float* d,
                                         uint32_t a0, uint32_t a1, uint32_t a2, uint32_t a3,
                                         uint32_t b0, uint32_t b1) {
    asm volatile(
        "mma.sync.aligned.m16n8k16.row.col.f32.bf16.bf16.f32 "
        "{%0,%1,%2,%3}, {%4,%5,%6,%7}, {%8,%9}, {%0,%1,%2,%3};"
        : "+f"(d[0]), "+f"(d[1]), "+f"(d[2]), "+f"(d[3])
        : "r"(a0), "r"(a1), "r"(a2), "r"(a3), "r"(b0), "r"(b1));
}

__device__ __forceinline__ void ldm_x4(uint32_t& r0, uint32_t& r1, uint32_t& r2, uint32_t& r3,
                                       uint32_t addr) {
    asm volatile("ldmatrix.sync.aligned.m8n8.x4.shared.b16 {%0,%1,%2,%3}, [%4];"
                 : "=r"(r0), "=r"(r1), "=r"(r2), "=r"(r3) : "r"(addr));
}

__device__ __forceinline__ uint32_t smem_u32(const void* p) {
    return (uint32_t)__cvta_generic_to_shared(p);
}

__device__ __forceinline__ void cp_async16(uint32_t dst, const void* src) {
    asm volatile("cp.async.cg.shared.global [%0], [%1], 16;" :: "r"(dst), "l"(src));
}
#define CP_COMMIT() asm volatile("cp.async.commit_group;" ::: "memory")
#define CP_WAIT(n)  asm volatile("cp.async.wait_group %0;" :: "n"(n) : "memory")

__device__ __forceinline__ uint32_t pack2(__nv_bfloat16 a, __nv_bfloat16 b) {
    return (uint32_t)__bfloat16_as_ushort(a) | ((uint32_t)__bfloat16_as_ushort(b) << 16);
}

__device__ __forceinline__ void split4(float4 v, uint2& hp, uint2& lp) {
    __nv_bfloat16 h0 = __float2bfloat16(v.x), h1 = __float2bfloat16(v.y);
    __nv_bfloat16 h2 = __float2bfloat16(v.z), h3 = __float2bfloat16(v.w);
    __nv_bfloat16 l0 = __float2bfloat16(v.x - __bfloat162float(h0));
    __nv_bfloat16 l1 = __float2bfloat16(v.y - __bfloat162float(h1));
    __nv_bfloat16 l2 = __float2bfloat16(v.z - __bfloat162float(h2));
    __nv_bfloat16 l3 = __float2bfloat16(v.w - __bfloat162float(h3));
    hp.x = pack2(h0, h1); hp.y = pack2(h2, h3);
    lp.x = pack2(l0, l1); lp.y = pack2(l2, l3);
}

__device__ __forceinline__ void store_hilo4(__nv_bfloat16* hi, __nv_bfloat16* lo,
                                            uint32_t off, float4 v) {
    uint2 hp, lp;
    split4(v, hp, lp);
    *(uint2*)(hi + off) = hp;
    *(uint2*)(lo + off) = lp;
}

__device__ __forceinline__ float warpRedMax(float v) {
    #pragma unroll
    for (int o = 16; o > 0; o >>= 1) v = fmaxf(v, __shfl_xor_sync(0xffffffffu, v, o));
    return v;
}
__device__ __forceinline__ float warpRedSum(float v) {
    #pragma unroll
    for (int o = 16; o > 0; o >>= 1) v += __shfl_xor_sync(0xffffffffu, v, o);
    return v;
}

// MMA over a chunk with row stride CWelems; KSTEPS ksteps of 16.
template<int CWE, int KSTEPS>
__device__ __forceinline__ void mma_chunk_t(float acc[16][4],
                                            uint32_t aHi, uint32_t aLo,
                                            uint32_t bHi, uint32_t bLo) {
    #pragma unroll
    for (int ks = 0; ks < KSTEPS; ++ks) {
        const uint32_t kb = ks * 32;   // 16 bf16 = 32 bytes
        uint32_t ah0, ah1, ah2, ah3, al0, al1, al2, al3;
        ldm_x4(ah0, ah1, ah2, ah3, aHi + kb);
        ldm_x4(al0, al1, al2, al3, aLo + kb);
        #pragma unroll
        for (int nt = 0; nt < 16; nt += 2) {
            const uint32_t bo = nt * (8 * CWE * 2) + kb;
            uint32_t bh0, bh1, bh2, bh3, bl0, bl1, bl2, bl3;
            ldm_x4(bh0, bh1, bh2, bh3, bHi + bo);
            ldm_x4(bl0, bl1, bl2, bl3, bLo + bo);
            mma_bf16(acc[nt],     ah0, ah1, ah2, ah3, bh0, bh1);
            mma_bf16(acc[nt],     ah0, ah1, ah2, ah3, bl0, bl1);
            mma_bf16(acc[nt],     al0, al1, al2, al3, bh0, bh1);
            mma_bf16(acc[nt + 1], ah0, ah1, ah2, ah3, bh2, bh3);
            mma_bf16(acc[nt + 1], ah0, ah1, ah2, ah3, bl2, bl3);
            mma_bf16(acc[nt + 1], al0, al1, al2, al3, bh2, bh3);
        }
    }
}

// ---------------------------------------------------------------------------
// K0a: V -> Vt (transposed) bf16 hi/lo
// ---------------------------------------------------------------------------
__global__ __launch_bounds__(256) void vt_kernel(const float* __restrict__ V) {
    __shared__ float t[32][33];
    const int k0 = blockIdx.x * 32, n0 = blockIdx.y * 32, bh = blockIdx.z;
    const int tid = threadIdx.x, c = tid & 31, r0 = tid >> 5;
    const float* Vb = V + (size_t)bh * S_ * D_;
    #pragma unroll
    for (int rr = r0; rr < 32; rr += 8)
        t[rr][c] = Vb[(size_t)(k0 + rr) * D_ + n0 + c];
    __syncthreads();
    __nv_bfloat16* Hb = g_VtHi + (size_t)bh * D_ * S_;
    __nv_bfloat16* Lb = g_VtLo + (size_t)bh * D_ * S_;
    #pragma unroll
    for (int rr = r0; rr < 32; rr += 8) {
        float x = t[c][rr];
        __nv_bfloat16 h = __float2bfloat16(x);
        __nv_bfloat16 l = __float2bfloat16(x - __bfloat162float(h));
        size_t o = (size_t)(n0 + rr) * S_ + k0 + c;
        Hb[o] = h;
        Lb[o] = l;
    }
}

// ---------------------------------------------------------------------------
// K0b: Q,K -> hi/lo bf16 (natural layout), elementwise
// ---------------------------------------------------------------------------
__global__ __launch_bounds__(256) void qk_prep_kernel(
    const float* __restrict__ Q, const float* __restrict__ K)
{
    const size_t i4 = ((size_t)blockIdx.x * 256 + threadIdx.x) * 4;  // elem index
    uint2 hp, lp;
    float4 q = *(const float4*)&Q[i4];
    split4(q, hp, lp);
    *(uint2*)&g_QHi[i4] = hp;
    *(uint2*)&g_QLo[i4] = lp;
    float4 k = *(const float4*)&K[i4];
    split4(k, hp, lp);
    *(uint2*)&g_KHi[i4] = hp;
    *(uint2*)&g_KLo[i4] = lp;
}

// ---------------------------------------------------------------------------
// K1: scores = Q K^T * scale + mask -> attn scratch. 128x128 tile per CTA.
// Operands pre-split in gmem; tiles loaded via cp.async, 32-wide k-chunks,
// double-buffered (issue ch+1, MMA ch). Window CTAs write final zeros.
// ---------------------------------------------------------------------------
__global__ __launch_bounds__(256, 2) void scores_mma_kernel(
    const int* __restrict__ mask, float* __restrict__ attn)
{
    const int bh = blockIdx.z, b = bh >> 4;
    const int i0 = blockIdx.y * 128, j0 = blockIdx.x * 128;
    const int tid = threadIdx.x;

    float* attnBase = attn + ((size_t)bh * S_ + i0) * S_ + j0;

    if (j0 + 128 <= (i0 * 4) / 5) {
        // fully-window tile: final attn here is exactly 0 — write it now
        const float4 z = make_float4(0.f, 0.f, 0.f, 0.f);
        #pragma unroll
        for (int it = 0; it < 16; ++it) {
            int idx = it * 256 + tid;
            *(float4*)&attnBase[(size_t)(idx >> 5) * S_ + ((idx & 31) << 2)] = z;
        }
        return;
    }

    extern __shared__ __nv_bfloat16 sm[];
    const uint32_t smBase = smem_u32(sm);

    const __nv_bfloat16* Qh = g_QHi + ((size_t)bh * S_ + i0) * D_;
    const __nv_bfloat16* Ql = g_QLo + ((size_t)bh * S_ + i0) * D_;
    const __nv_bfloat16* Kh = g_KHi + ((size_t)bh * S_ + j0) * D_;
    const __nv_bfloat16* Kl = g_KLo + ((size_t)bh * S_ + j0) * D_;

    const int lane = tid & 31, warp = tid >> 5;
    const int g = lane >> 2, c = lane & 3;
    const int m0 = warp * 16;

    float acc[16][4];
    #pragma unroll
    for (int nt = 0; nt < 16; ++nt)
        #pragma unroll
        for (int q = 0; q < 4; ++q) acc[nt][q] = 0.0f;

    // ldmatrix per-thread offsets (bytes) within a chunk stage
    const uint32_t aRowOff = ((m0 + (lane & 15)) * CWS + (lane >> 4) * 8) * 2;
    const uint32_t bRowOff = ((((lane >> 4) << 3) + (lane & 7)) * CWS + ((lane >> 3) & 1) * 8) * 2;

    // cp.async per-thread mapping: row = tid>>1, 32 bytes at (tid&1)*32
    const int cpRow = tid >> 1;
    const int cpE = (tid & 1) * 16;               // elem offset within chunk row
    const uint32_t cpDst = (uint32_t)(cpRow * CWS + cpE) * 2;   // byte offset in tile

    // issue chunk ch into stage st
    auto issue = [&](int ch, int st) {
        const int kc = ch * 32;
        const uint32_t sb = smBase + (uint32_t)st * (4 * CHS_ELEMS * 2);
        const size_t so = (size_t)cpRow * D_ + kc + cpE;
        cp_async16(sb + cpDst,                        Qh + so);
        cp_async16(sb + cpDst + 16,                   Qh + so + 8);
        cp_async16(sb + CHS_ELEMS * 2 + cpDst,        Ql + so);
        cp_async16(sb + CHS_ELEMS * 2 + cpDst + 16,   Ql + so + 8);
        cp_async16(sb + 2 * CHS_ELEMS * 2 + cpDst,      Kh + so);
        cp_async16(sb + 2 * CHS_ELEMS * 2 + cpDst + 16, Kh + so + 8);
        cp_async16(sb + 3 * CHS_ELEMS * 2 + cpDst,      Kl + so);
        cp_async16(sb + 3 * CHS_ELEMS * 2 + cpDst + 16, Kl + so + 8);
    };

    issue(0, 0);
    CP_COMMIT();

    #pragma unroll
    for (int ch = 0; ch < 4; ++ch) {
        CP_WAIT(0);          // chunk ch landed
        __syncthreads();     // also: all warps done MMA(ch-1) -> other stage reusable
        if (ch < 3) {
            issue(ch + 1, (ch + 1) & 1);
            CP_COMMIT();
        }
        const uint32_t sb = smBase + (uint32_t)(ch & 1) * (4 * CHS_ELEMS * 2);
        mma_chunk_t<CWS, 2>(acc,
                            sb + aRowOff,
                            sb + CHS_ELEMS * 2 + aRowOff,
                            sb + 2 * CHS_ELEMS * 2 + bRowOff,
                            sb + 3 * CHS_ELEMS * 2 + bRowOff);
    }
    __syncthreads();   // all warps done reading smem; reuse as fp32 staging

    float* stg = (float*)sm;
    #pragma unroll
    for (int nt = 0; nt < 16; ++nt) {
        *(float2*)&stg[(m0 + g) * SGW + nt * 8 + 2 * c]     = make_float2(acc[nt][0], acc[nt][1]);
        *(float2*)&stg[(m0 + g + 8) * SGW + nt * 8 + 2 * c] = make_float2(acc[nt][2], acc[nt][3]);
    }
    __syncthreads();

    const int* mB = mask + (size_t)b * S_ * S_;
    #pragma unroll
    for (int it = 0; it < 16; ++it) {
        int idx = it * 256 + tid;
        int r = idx >> 5, cc = (idx & 31) * 4;
        int i = i0 + r, thr = (i * 4) / 5, j = j0 + cc;
        int4 mv = *(const int4*)&mB[(size_t)i * S_ + j];
        float4 s = *(float4*)&stg[r * SGW + cc];
        float4 v;
        v.x = (mv.x || (j + 0) < thr) ? NEG : s.x * SCALE;
        v.y = (mv.y || (j + 1) < thr) ? NEG : s.y * SCALE;
        v.z = (mv.z || (j + 2) < thr) ? NEG : s.z * SCALE;
        v.w = (mv.w || (j + 3) < thr) ? NEG : s.w * SCALE;
        *(float4*)&attnBase[(size_t)r * S_ + cc] = v;
    }
}

// ---------------------------------------------------------------------------
// K2: row softmax over [jStart, S) only. [0, jStart) already holds final zeros.
// ---------------------------------------------------------------------------
__global__ __launch_bounds__(256) void softmax_kernel(float* __restrict__ attn)
{
    const int row = blockIdx.x;
    const int i = row & (S_ - 1);
    const int i0 = i & ~127;
    const int jStart = (((i0 * 4) / 5) >> 7) << 7;
    float* p = attn + (size_t)row * S_;
    const int tid = threadIdx.x;

    const int n4 = (S_ - jStart) >> 2;
    float4* p4 = (float4*)(p + jStart);
    const bool val0 = tid < n4;
    const bool val1 = tid + 256 < n4;

    float4 v0 = make_float4(NEG, NEG, NEG, NEG);
    float4 v1 = make_float4(NEG, NEG, NEG, NEG);
    if (val0) v0 = p4[tid];
    if (val1) v1 = p4[tid + 256];

    __shared__ float red[8];

    float m = fmaxf(fmaxf(fmaxf(v0.x, v0.y), fmaxf(v0.z, v0.w)),
                    fmaxf(fmaxf(v1.x, v1.y), fmaxf(v1.z, v1.w)));
    m = warpRedMax(m);
    if ((tid & 31) == 0) red[tid >> 5] = m;
    __syncthreads();
    float bm = red[0];
    #pragma unroll
    for (int k = 1; k < 8; ++k) bm = fmaxf(bm, red[k]);
    __syncthreads();

    v0.x = __expf(v0.x - bm); v0.y = __expf(v0.y - bm);
    v0.z = __expf(v0.z - bm); v0.w = __expf(v0.w - bm);
    v1.x = __expf(v1.x - bm); v1.y = __expf(v1.y - bm);
    v1.z = __expf(v1.z - bm); v1.w = __expf(v1.w - bm);

    float s = 0.0f;
    if (val0) s += (v0.x + v0.y) + (v0.z + v0.w);
    if (val1) s += (v1.x + v1.y) + (v1.z + v1.w);
    s = warpRedSum(s);
    if ((tid & 31) == 0) red[tid >> 5] = s;
    __syncthreads();
    float bs = 0.0f;
    #pragma unroll
    for (int k = 0; k < 8; ++k) bs += red[k];

    const float inv = 1.0f / bs;
    if (val0) {
        v0.x *= inv; v0.y *= inv; v0.z *= inv; v0.w *= inv;
        p4[tid] = v0;
    }
    if (val1) {
        v1.x *= inv; v1.y *= inv; v1.z *= inv; v1.w *= inv;
        p4[tid + 256] = v1;
    }
}

// ---------------------------------------------------------------------------
// K3: context = attn @ V. 128x128 output per CTA. (R11 structure)
// P single-buffered (fp32->hi/lo convert); V double-buffered via cp.async.
// ---------------------------------------------------------------------------
__global__ __launch_bounds__(256, 2) void context_mma_kernel(
    const float* __restrict__ attn, float* __restrict__ ctx)
{
    const int i0 = blockIdx.x * 128, bh = blockIdx.y;
    const int tid = threadIdx.x;

    extern __shared__ __nv_bfloat16 sm[];
    __nv_bfloat16* Phi = sm;
    __nv_bfloat16* Plo = sm + CH_ELEMS;
    __nv_bfloat16* Vst = sm + 2 * CH_ELEMS;

    const float* Pb = attn + ((size_t)bh * S_ + i0) * S_;
    const __nv_bfloat16* VtH = g_VtHi + (size_t)bh * D_ * S_;
    const __nv_bfloat16* VtL = g_VtLo + (size_t)bh * D_ * S_;

    const int lane = tid & 31, warp = tid >> 5;
    const int g = lane >> 2, c = lane & 3;
    const int m0 = warp * 16;

    float acc[16][4];
    #pragma unroll
    for (int nt = 0; nt < 16; ++nt)
        #pragma unroll
        for (int q = 0; q < 4; ++q) acc[nt][q] = 0.0f;

    const uint32_t aRowOff = ((m0 + (lane & 15)) * CW + (lane >> 4) * 8) * 2;
    const uint32_t bRowOff = ((((lane >> 4) << 3) + (lane & 7)) * CW + ((lane >> 3) & 1) * 8) * 2;
    const uint32_t aHiA = smem_u32(Phi) + aRowOff;
    const uint32_t aLoA = smem_u32(Plo) + aRowOff;
    const uint32_t vBase = smem_u32(Vst);
    const uint32_t bHiA0 = vBase + bRowOff;
    const uint32_t bLoA0 = vBase + CH_ELEMS * 2 + bRowOff;

    const int vn = tid >> 3, vk8 = (tid & 7) << 3;

    const int ch0 = (((i0 * 4) / 5) >> 7) * 2;

    {
        const int k0g = ch0 * 64;
        const uint32_t st = (uint32_t)(ch0 & 1) * (2 * CH_ELEMS * 2);
        #pragma unroll
        for (int it = 0; it < 4; ++it) {
            int n = vn + it * 32;
            uint32_t doff = (n * CW + vk8) * 2;
            cp_async16(vBase + st + doff, &VtH[(size_t)n * S_ + k0g + vk8]);
            cp_async16(vBase + st + CH_ELEMS * 2 + doff, &VtL[(size_t)n * S_ + k0g + vk8]);
        }
        CP_COMMIT();
    }

    for (int ch = ch0; ch < 32; ++ch) {
        if (ch > ch0) __syncthreads();
        const int k0g = ch * 64;
        #pragma unroll
        for (int it = 0; it < 8; ++it) {
            int idx = it * 256 + tid;
            int row = idx >> 4, c4 = (idx & 15) << 2;
            store_hilo4(Phi, Plo, row * CW + c4,
                        *(const float4*)&Pb[(size_t)row * S_ + k0g + c4]);
        }
        if (ch + 1 < 32) {
            const int k1g = (ch + 1) * 64;
            const uint32_t st = (uint32_t)((ch + 1) & 1) * (2 * CH_ELEMS * 2);
            #pragma unroll
            for (int it = 0; it < 4; ++it) {
                int n = vn + it * 32;
                uint32_t doff = (n * CW + vk8) * 2;
                cp_async16(vBase + st + doff, &VtH[(size_t)n * S_ + k1g + vk8]);
                cp_async16(vBase + st + CH_ELEMS * 2 + doff, &VtL[(size_t)n * S_ + k1g + vk8]);
            }
            CP_COMMIT();
            CP_WAIT(1);
        } else {
            CP_WAIT(0);
        }
        __syncthreads();
        const uint32_t st = (uint32_t)(ch & 1) * (2 * CH_ELEMS * 2);
        mma_chunk_t<CW, 4>(acc, aHiA, aLoA, bHiA0 + st, bLoA0 + st);
    }
    __syncthreads();

    float* stg = (float*)sm;
    #pragma unroll
    for (int nt = 0; nt < 16; ++nt) {
        *(float2*)&stg[(m0 + g) * SGW + nt * 8 + 2 * c]     = make_float2(acc[nt][0], acc[nt][1]);
        *(float2*)&stg[(m0 + g + 8) * SGW + nt * 8 + 2 * c] = make_float2(acc[nt][2], acc[nt][3]);
    }
    __syncthreads();

    #pragma unroll
    for (int it = 0; it < 16; ++it) {
        int idx = it * 256 + tid;
        int r = idx >> 5, c4 = (idx & 31) << 2;
        *(float4*)&ctx[((size_t)bh * S_ + i0 + r) * D_ + c4] = *(float4*)&stg[r * SGW + c4];
    }
}

// ---------------------------------------------------------------------------
// kernel_launch
// ---------------------------------------------------------------------------
extern "C" void kernel_launch(void* const* d_in, const int* in_sizes, int n_in,
                              void* d_out, int out_size)
{
    const float* Q    = (const float*)d_in[0];
    const float* K    = (const float*)d_in[1];
    const float* V    = (const float*)d_in[2];
    const int*   mask = (const int*)d_in[3];

    float* out  = (float*)d_out;
    float* ctx  = out;
    float* attn = out + (size_t)B_ * H_ * S_ * D_;

    static bool attrs_set = false;
    if (!attrs_set) {
        cudaFuncSetAttribute(scores_mma_kernel, cudaFuncAttributeMaxDynamicSharedMemorySize, SM_BYTES_S);
        cudaFuncSetAttribute(context_mma_kernel, cudaFuncAttributeMaxDynamicSharedMemorySize, SM_BYTES_C);
        attrs_set = true;
    }

    vt_kernel<<<dim3(S_ / 32, D_ / 32, B_ * H_), 256>>>(V);
    qk_prep_kernel<<<8192, 256>>>(Q, K);   // 32*2048*128 / (256*4)

    dim3 g1(S_ / 128, S_ / 128, B_ * H_);
    scores_mma_kernel<<<g1, 256, SM_BYTES_S>>>(mask, attn);

    softmax_kernel<<<B_ * H_ * S_, 256>>>(attn);

    dim3 g3(S_ / 128, B_ * H_);
    context_mma_kernel<<<g3, 256, SM_BYTES_C>>>(attn, ctx);

    (void)in_sizes; (void)n_in; (void)out_size;
}

// round 14
// speedup vs baseline: 1.1667x; 1.0112x over previous
#include <cuda_runtime.h>
#include <cuda_bf16.h>
#include <cstdint>

#define B_ 2
#define H_ 16
#define S_ 2048
#define D_ 128
#define SCALE 0.08838834764831845f   // 1/sqrt(128)
#define NEG (-1e9f)

// ctx kernel chunking
#define CW 72                        // 64 data + 8 pad (bf16 elems)
#define CH_ELEMS (128 * CW)
#define SM_BYTES_C (6 * CH_ELEMS * 2)   // P hi/lo + V hi/lo x2 stages = 110592 B

// scores kernel chunking (32-wide, double-buffered, cp.async direct)
#define CWS 40                       // 32 data + 8 pad
#define CHS_ELEMS (128 * CWS)        // 5120
#define SM_BYTES_S (8 * CHS_ELEMS * 2)  // 2 stages x 4 tiles = 81920 B

#define SGW 132                      // fp32 staging row stride (floats)

// Pre-split operands in global memory (bf16 hi/lo)
__device__ __align__(16) __nv_bfloat16 g_VtHi[(size_t)32 * 128 * 2048];  // V transposed
__device__ __align__(16) __nv_bfloat16 g_VtLo[(size_t)32 * 128 * 2048];
__device__ __align__(16) __nv_bfloat16 g_QHi[(size_t)32 * 2048 * 128];   // natural layout
__device__ __align__(16) __nv_bfloat16 g_QLo[(size_t)32 * 2048 * 128];
__device__ __align__(16) __nv_bfloat16 g_KHi[(size_t)32 * 2048 * 128];
__device__ __align__(16) __nv_bfloat16 g_KLo[(size_t)32 * 2048 * 128];

// ---------------------------------------------------------------------------
__device__ __forceinline__ void mma_bf16(float* d,
                                         uint32_t a0, uint32_t a1, uint32_t a2, uint32_t a3,
                                         uint32_t b0, uint32_t b1) {
    asm volatile(
        "mma.sync.aligned.m16n8k16.row.col.f32.bf16.bf16.f32 "
        "{%0,%1,%2,%3}, {%4,%5,%6,%7}, {%8,%9}, {%0,%1,%2,%3};"
        : "+f"(d[0]), "+f"(d[1]), "+f"(d[2]), "+f"(d[3])
        : "r"(a0), "r"(a1), "r"(a2), "r"(a3), "r"(b0), "r"(b1));
}

__device__ __forceinline__ void ldm_x4(uint32_t& r0, uint32_t& r1, uint32_t& r2, uint32_t& r3,
                                       uint32_t addr) {
    asm volatile("ldmatrix.sync.aligned.m8n8.x4.shared.b16 {%0,%1,%2,%3}, [%4];"
                 : "=r"(r0), "=r"(r1), "=r"(r2), "=r"(r3) : "r"(addr));
}

__device__ __forceinline__ uint32_t smem_u32(const void* p) {
    return (uint32_t)__cvta_generic_to_shared(p);
}

__device__ __forceinline__ void cp_async16(uint32_t dst, const void* src) {
    asm volatile("cp.async.cg.shared.global [%0], [%1], 16;" :: "r"(dst), "l"(src));
}
#define CP_COMMIT() asm volatile("cp.async.commit_group;" ::: "memory")
#define CP_WAIT(n)  asm volatile("cp.async.wait_group %0;" :: "n"(n) : "memory")

__device__ __forceinline__ uint32_t pack2(__nv_bfloat16 a, __nv_bfloat16 b) {
    return (uint32_t)__bfloat16_as_ushort(a) | ((uint32_t)__bfloat16_as_ushort(b) << 16);
}

__device__ __forceinline__ void split4(float4 v, uint2& hp, uint2& lp) {
    __nv_bfloat16 h0 = __float2bfloat16(v.x), h1 = __float2bfloat16(v.y);
    __nv_bfloat16 h2 = __float2bfloat16(v.z), h3 = __float2bfloat16(v.w);
    __nv_bfloat16 l0 = __float2bfloat16(v.x - __bfloat162float(h0));
    __nv_bfloat16 l1 = __float2bfloat16(v.y - __bfloat162float(h1));
    __nv_bfloat16 l2 = __float2bfloat16(v.z - __bfloat162float(h2));
    __nv_bfloat16 l3 = __float2bfloat16(v.w - __bfloat162float(h3));
    hp.x = pack2(h0, h1); hp.y = pack2(h2, h3);
    lp.x = pack2(l0, l1); lp.y = pack2(l2, l3);
}

__device__ __forceinline__ void store_hilo4(__nv_bfloat16* hi, __nv_bfloat16* lo,
                                            uint32_t off, float4 v) {
    uint2 hp, lp;
    split4(v, hp, lp);
    *(uint2*)(hi + off) = hp;
    *(uint2*)(lo + off) = lp;
}

__device__ __forceinline__ float warpRedMax(float v) {
    #pragma unroll
    for (int o = 16; o > 0; o >>= 1) v = fmaxf(v, __shfl_xor_sync(0xffffffffu, v, o));
    return v;
}
__device__ __forceinline__ float warpRedSum(float v) {
    #pragma unroll
    for (int o = 16; o > 0; o >>= 1) v += __shfl_xor_sync(0xffffffffu, v, o);
    return v;
}

// ---------------------------------------------------------------------------
// MMA over a chunk. Warp tile = 32 (M) x 64 (N): acc[2][8][4]
// (2 m16 sub-blocks x 8 n8 tiles). aHi/aLo point at the warp's first m16
// block row; bHi/bLo at the warp's first n row.
// ---------------------------------------------------------------------------
template<int CWE, int KSTEPS>
__device__ __forceinline__ void mma_chunk_t(float acc[2][8][4],
                                            uint32_t aHi, uint32_t aLo,
                                            uint32_t bHi, uint32_t bLo) {
    #pragma unroll
    for (int ks = 0; ks < KSTEPS; ++ks) {
        const uint32_t kb = ks * 32;   // 16 bf16 = 32 bytes
        uint32_t ah[2][4], al[2][4];
        #pragma unroll
        for (int s = 0; s < 2; ++s) {
            const uint32_t so = (uint32_t)s * (16 * CWE * 2);
            ldm_x4(ah[s][0], ah[s][1], ah[s][2], ah[s][3], aHi + so + kb);
            ldm_x4(al[s][0], al[s][1], al[s][2], al[s][3], aLo + so + kb);
        }
        #pragma unroll
        for (int np = 0; np < 4; ++np) {   // each covers 2 n-tiles (16 rows of B)
            const uint32_t bo = (uint32_t)np * (16 * CWE * 2) + kb;
            uint32_t bh0, bh1, bh2, bh3, bl0, bl1, bl2, bl3;
            ldm_x4(bh0, bh1, bh2, bh3, bHi + bo);
            ldm_x4(bl0, bl1, bl2, bl3, bLo + bo);
            #pragma unroll
            for (int s = 0; s < 2; ++s) {
                mma_bf16(acc[s][2*np],     ah[s][0], ah[s][1], ah[s][2], ah[s][3], bh0, bh1);
                mma_bf16(acc[s][2*np],     ah[s][0], ah[s][1], ah[s][2], ah[s][3], bl0, bl1);
                mma_bf16(acc[s][2*np],     al[s][0], al[s][1], al[s][2], al[s][3], bh0, bh1);
                mma_bf16(acc[s][2*np + 1], ah[s][0], ah[s][1], ah[s][2], ah[s][3], bh2, bh3);
                mma_bf16(acc[s][2*np + 1], ah[s][0], ah[s][1], ah[s][2], ah[s][3], bl2, bl3);
                mma_bf16(acc[s][2*np + 1], al[s][0], al[s][1], al[s][2], al[s][3], bh2, bh3);
            }
        }
    }
}

// ---------------------------------------------------------------------------
// K0a: V -> Vt (transposed) bf16 hi/lo
// ---------------------------------------------------------------------------
__global__ __launch_bounds__(256) void vt_kernel(const float* __restrict__ V) {
    __shared__ float t[32][33];
    const int k0 = blockIdx.x * 32, n0 = blockIdx.y * 32, bh = blockIdx.z;
    const int tid = threadIdx.x, c = tid & 31, r0 = tid >> 5;
    const float* Vb = V + (size_t)bh * S_ * D_;
    #pragma unroll
    for (int rr = r0; rr < 32; rr += 8)
        t[rr][c] = Vb[(size_t)(k0 + rr) * D_ + n0 + c];
    __syncthreads();
    __nv_bfloat16* Hb = g_VtHi + (size_t)bh * D_ * S_;
    __nv_bfloat16* Lb = g_VtLo + (size_t)bh * D_ * S_;
    #pragma unroll
    for (int rr = r0; rr < 32; rr += 8) {
        float x = t[c][rr];
        __nv_bfloat16 h = __float2bfloat16(x);
        __nv_bfloat16 l = __float2bfloat16(x - __bfloat162float(h));
        size_t o = (size_t)(n0 + rr) * S_ + k0 + c;
        Hb[o] = h;
        Lb[o] = l;
    }
}

// ---------------------------------------------------------------------------
// K0b: Q,K -> hi/lo bf16 (natural layout), elementwise
// ---------------------------------------------------------------------------
__global__ __launch_bounds__(256) void qk_prep_kernel(
    const float* __restrict__ Q, const float* __restrict__ K)
{
    const size_t i4 = ((size_t)blockIdx.x * 256 + threadIdx.x) * 4;
    uint2 hp, lp;
    float4 q = *(const float4*)&Q[i4];
    split4(q, hp, lp);
    *(uint2*)&g_QHi[i4] = hp;
    *(uint2*)&g_QLo[i4] = lp;
    float4 k = *(const float4*)&K[i4];
    split4(k, hp, lp);
    *(uint2*)&g_KHi[i4] = hp;
    *(uint2*)&g_KLo[i4] = lp;
}

// ---------------------------------------------------------------------------
// K1: scores = Q K^T * scale + mask -> attn scratch. 128x128 tile per CTA.
// cp.async 32-wide k-chunks, double buffered. Warp tile 32x64.
// ---------------------------------------------------------------------------
__global__ __launch_bounds__(256, 2) void scores_mma_kernel(
    const int* __restrict__ mask, float* __restrict__ attn)
{
    const int bh = blockIdx.z, b = bh >> 4;
    const int i0 = blockIdx.y * 128, j0 = blockIdx.x * 128;
    const int tid = threadIdx.x;

    float* attnBase = attn + ((size_t)bh * S_ + i0) * S_ + j0;

    if (j0 + 128 <= (i0 * 4) / 5) {
        const float4 z = make_float4(0.f, 0.f, 0.f, 0.f);
        #pragma unroll
        for (int it = 0; it < 16; ++it) {
            int idx = it * 256 + tid;
            *(float4*)&attnBase[(size_t)(idx >> 5) * S_ + ((idx & 31) << 2)] = z;
        }
        return;
    }

    extern __shared__ __nv_bfloat16 sm[];
    const uint32_t smBase = smem_u32(sm);

    const __nv_bfloat16* Qh = g_QHi + ((size_t)bh * S_ + i0) * D_;
    const __nv_bfloat16* Ql = g_QLo + ((size_t)bh * S_ + i0) * D_;
    const __nv_bfloat16* Kh = g_KHi + ((size_t)bh * S_ + j0) * D_;
    const __nv_bfloat16* Kl = g_KLo + ((size_t)bh * S_ + j0) * D_;

    const int lane = tid & 31, warp = tid >> 5;
    const int g = lane >> 2, c = lane & 3;
    const int mb2 = warp & 3;        // M block of 32 rows
    const int nb  = warp >> 2;       // N block of 64 cols

    float acc[2][8][4];
    #pragma unroll
    for (int s = 0; s < 2; ++s)
        #pragma unroll
        for (int nt = 0; nt < 8; ++nt)
            #pragma unroll
            for (int q = 0; q < 4; ++q) acc[s][nt][q] = 0.0f;

    // ldmatrix per-thread offsets (bytes) within a chunk stage
    const uint32_t aRowOff = ((mb2 * 32 + (lane & 15)) * CWS + (lane >> 4) * 8) * 2;
    const uint32_t bRowOff = ((nb * 64 + ((lane >> 4) << 3) + (lane & 7)) * CWS
                              + ((lane >> 3) & 1) * 8) * 2;

    // cp.async per-thread mapping: row = tid>>1, 32 bytes at (tid&1)*32
    const int cpRow = tid >> 1;
    const int cpE = (tid & 1) * 16;
    const uint32_t cpDst = (uint32_t)(cpRow * CWS + cpE) * 2;

    auto issue = [&](int ch, int st) {
        const int kc = ch * 32;
        const uint32_t sb = smBase + (uint32_t)st * (4 * CHS_ELEMS * 2);
        const size_t so = (size_t)cpRow * D_ + kc + cpE;
        cp_async16(sb + cpDst,                          Qh + so);
        cp_async16(sb + cpDst + 16,                     Qh + so + 8);
        cp_async16(sb + CHS_ELEMS * 2 + cpDst,          Ql + so);
        cp_async16(sb + CHS_ELEMS * 2 + cpDst + 16,     Ql + so + 8);
        cp_async16(sb + 2 * CHS_ELEMS * 2 + cpDst,      Kh + so);
        cp_async16(sb + 2 * CHS_ELEMS * 2 + cpDst + 16, Kh + so + 8);
        cp_async16(sb + 3 * CHS_ELEMS * 2 + cpDst,      Kl + so);
        cp_async16(sb + 3 * CHS_ELEMS * 2 + cpDst + 16, Kl + so + 8);
    };

    issue(0, 0);
    CP_COMMIT();

    #pragma unroll
    for (int ch = 0; ch < 4; ++ch) {
        CP_WAIT(0);
        __syncthreads();
        if (ch < 3) {
            issue(ch + 1, (ch + 1) & 1);
            CP_COMMIT();
        }
        const uint32_t sb = smBase + (uint32_t)(ch & 1) * (4 * CHS_ELEMS * 2);
        mma_chunk_t<CWS, 2>(acc,
                            sb + aRowOff,
                            sb + CHS_ELEMS * 2 + aRowOff,
                            sb + 2 * CHS_ELEMS * 2 + bRowOff,
                            sb + 3 * CHS_ELEMS * 2 + bRowOff);
    }
    __syncthreads();   // reuse smem as fp32 staging

    float* stg = (float*)sm;
    #pragma unroll
    for (int s = 0; s < 2; ++s) {
        int r0 = mb2 * 32 + s * 16 + g;
        #pragma unroll
        for (int nt = 0; nt < 8; ++nt) {
            int cc = nb * 64 + nt * 8 + 2 * c;
            *(float2*)&stg[r0 * SGW + cc]       = make_float2(acc[s][nt][0], acc[s][nt][1]);
            *(float2*)&stg[(r0 + 8) * SGW + cc] = make_float2(acc[s][nt][2], acc[s][nt][3]);
        }
    }
    __syncthreads();

    const int* mB = mask + (size_t)b * S_ * S_;
    #pragma unroll
    for (int it = 0; it < 16; ++it) {
        int idx = it * 256 + tid;
        int r = idx >> 5, cc = (idx & 31) * 4;
        int i = i0 + r, thr = (i * 4) / 5, j = j0 + cc;
        int4 mv = *(const int4*)&mB[(size_t)i * S_ + j];
        float4 s = *(float4*)&stg[r * SGW + cc];
        float4 v;
        v.x = (mv.x || (j + 0) < thr) ? NEG : s.x * SCALE;
        v.y = (mv.y || (j + 1) < thr) ? NEG : s.y * SCALE;
        v.z = (mv.z || (j + 2) < thr) ? NEG : s.z * SCALE;
        v.w = (mv.w || (j + 3) < thr) ? NEG : s.w * SCALE;
        *(float4*)&attnBase[(size_t)r * S_ + cc] = v;
    }
}

// ---------------------------------------------------------------------------
// K2: row softmax over [jStart, S) only. [0, jStart) already holds final zeros.
// ---------------------------------------------------------------------------
__global__ __launch_bounds__(256) void softmax_kernel(float* __restrict__ attn)
{
    const int row = blockIdx.x;
    const int i = row & (S_ - 1);
    const int i0 = i & ~127;
    const int jStart = (((i0 * 4) / 5) >> 7) << 7;
    float* p = attn + (size_t)row * S_;
    const int tid = threadIdx.x;

    const int n4 = (S_ - jStart) >> 2;
    float4* p4 = (float4*)(p + jStart);
    const bool val0 = tid < n4;
    const bool val1 = tid + 256 < n4;

    float4 v0 = make_float4(NEG, NEG, NEG, NEG);
    float4 v1 = make_float4(NEG, NEG, NEG, NEG);
    if (val0) v0 = p4[tid];
    if (val1) v1 = p4[tid + 256];

    __shared__ float red[8];

    float m = fmaxf(fmaxf(fmaxf(v0.x, v0.y), fmaxf(v0.z, v0.w)),
                    fmaxf(fmaxf(v1.x, v1.y), fmaxf(v1.z, v1.w)));
    m = warpRedMax(m);
    if ((tid & 31) == 0) red[tid >> 5] = m;
    __syncthreads();
    float bm = red[0];
    #pragma unroll
    for (int k = 1; k < 8; ++k) bm = fmaxf(bm, red[k]);
    __syncthreads();

    v0.x = __expf(v0.x - bm); v0.y = __expf(v0.y - bm);
    v0.z = __expf(v0.z - bm); v0.w = __expf(v0.w - bm);
    v1.x = __expf(v1.x - bm); v1.y = __expf(v1.y - bm);
    v1.z = __expf(v1.z - bm); v1.w = __expf(v1.w - bm);

    float s = 0.0f;
    if (val0) s += (v0.x + v0.y) + (v0.z + v0.w);
    if (val1) s += (v1.x + v1.y) + (v1.z + v1.w);
    s = warpRedSum(s);
    if ((tid & 31) == 0) red[tid >> 5] = s;
    __syncthreads();
    float bs = 0.0f;
    #pragma unroll
    for (int k = 0; k < 8; ++k) bs += red[k];

    const float inv = 1.0f / bs;
    if (val0) {
        v0.x *= inv; v0.y *= inv; v0.z *= inv; v0.w *= inv;
        p4[tid] = v0;
    }
    if (val1) {
        v1.x *= inv; v1.y *= inv; v1.z *= inv; v1.w *= inv;
        p4[tid + 256] = v1;
    }
}

// ---------------------------------------------------------------------------
// K3: context = attn @ V. 128x128 output per CTA. Warp tile 32x64.
// P single-buffered (fp32->hi/lo convert); V double-buffered via cp.async.
// ---------------------------------------------------------------------------
__global__ __launch_bounds__(256, 2) void context_mma_kernel(
    const float* __restrict__ attn, float* __restrict__ ctx)
{
    const int i0 = blockIdx.x * 128, bh = blockIdx.y;
    const int tid = threadIdx.x;

    extern __shared__ __nv_bfloat16 sm[];
    __nv_bfloat16* Phi = sm;
    __nv_bfloat16* Plo = sm + CH_ELEMS;
    __nv_bfloat16* Vst = sm + 2 * CH_ELEMS;

    const float* Pb = attn + ((size_t)bh * S_ + i0) * S_;
    const __nv_bfloat16* VtH = g_VtHi + (size_t)bh * D_ * S_;
    const __nv_bfloat16* VtL = g_VtLo + (size_t)bh * D_ * S_;

    const int lane = tid & 31, warp = tid >> 5;
    const int g = lane >> 2, c = lane & 3;
    const int mb2 = warp & 3;
    const int nb  = warp >> 2;

    float acc[2][8][4];
    #pragma unroll
    for (int s = 0; s < 2; ++s)
        #pragma unroll
        for (int nt = 0; nt < 8; ++nt)
            #pragma unroll
            for (int q = 0; q < 4; ++q) acc[s][nt][q] = 0.0f;

    const uint32_t aRowOff = ((mb2 * 32 + (lane & 15)) * CW + (lane >> 4) * 8) * 2;
    const uint32_t bRowOff = ((nb * 64 + ((lane >> 4) << 3) + (lane & 7)) * CW
                              + ((lane >> 3) & 1) * 8) * 2;
    const uint32_t aHiA = smem_u32(Phi) + aRowOff;
    const uint32_t aLoA = smem_u32(Plo) + aRowOff;
    const uint32_t vBase = smem_u32(Vst);
    const uint32_t bHiA0 = vBase + bRowOff;
    const uint32_t bLoA0 = vBase + CH_ELEMS * 2 + bRowOff;

    const int vn = tid >> 3, vk8 = (tid & 7) << 3;

    const int ch0 = (((i0 * 4) / 5) >> 7) * 2;

    {
        const int k0g = ch0 * 64;
        const uint32_t st = (uint32_t)(ch0 & 1) * (2 * CH_ELEMS * 2);
        #pragma unroll
        for (int it = 0; it < 4; ++it) {
            int n = vn + it * 32;
            uint32_t doff = (n * CW + vk8) * 2;
            cp_async16(vBase + st + doff, &VtH[(size_t)n * S_ + k0g + vk8]);
            cp_async16(vBase + st + CH_ELEMS * 2 + doff, &VtL[(size_t)n * S_ + k0g + vk8]);
        }
        CP_COMMIT();
    }

    for (int ch = ch0; ch < 32; ++ch) {
        if (ch > ch0) __syncthreads();
        const int k0g = ch * 64;
        #pragma unroll
        for (int it = 0; it < 8; ++it) {
            int idx = it * 256 + tid;
            int row = idx >> 4, c4 = (idx & 15) << 2;
            store_hilo4(Phi, Plo, row * CW + c4,
                        *(const float4*)&Pb[(size_t)row * S_ + k0g + c4]);
        }
        if (ch + 1 < 32) {
            const int k1g = (ch + 1) * 64;
            const uint32_t st = (uint32_t)((ch + 1) & 1) * (2 * CH_ELEMS * 2);
            #pragma unroll
            for (int it = 0; it < 4; ++it) {
                int n = vn + it * 32;
                uint32_t doff = (n * CW + vk8) * 2;
                cp_async16(vBase + st + doff, &VtH[(size_t)n * S_ + k1g + vk8]);
                cp_async16(vBase + st + CH_ELEMS * 2 + doff, &VtL[(size_t)n * S_ + k1g + vk8]);
            }
            CP_COMMIT();
            CP_WAIT(1);
        } else {
            CP_WAIT(0);
        }
        __syncthreads();
        const uint32_t st = (uint32_t)(ch & 1) * (2 * CH_ELEMS * 2);
        mma_chunk_t<CW, 4>(acc, aHiA, aLoA, bHiA0 + st, bLoA0 + st);
    }
    __syncthreads();

    float* stg = (float*)sm;
    #pragma unroll
    for (int s = 0; s < 2; ++s) {
        int r0 = mb2 * 32 + s * 16 + g;
        #pragma unroll
        for (int nt = 0; nt < 8; ++nt) {
            int cc = nb * 64 + nt * 8 + 2 * c;
            *(float2*)&stg[r0 * SGW + cc]       = make_float2(acc[s][nt][0], acc[s][nt][1]);
            *(float2*)&stg[(r0 + 8) * SGW + cc] = make_float2(acc[s][nt][2], acc[s][nt][3]);
        }
    }
    __syncthreads();

    #pragma unroll
    for (int it = 0; it < 16; ++it) {
        int idx = it * 256 + tid;
        int r = idx >> 5, c4 = (idx & 31) << 2;
        *(float4*)&ctx[((size_t)bh * S_ + i0 + r) * D_ + c4] = *(float4*)&stg[r * SGW + c4];
    }
}

// ---------------------------------------------------------------------------
// kernel_launch
// ---------------------------------------------------------------------------
extern "C" void kernel_launch(void* const* d_in, const int* in_sizes, int n_in,
                              void* d_out, int out_size)
{
    const float* Q    = (const float*)d_in[0];
    const float* K    = (const float*)d_in[1];
    const float* V    = (const float*)d_in[2];
    const int*   mask = (const int*)d_in[3];

    float* out  = (float*)d_out;
    float* ctx  = out;
    float* attn = out + (size_t)B_ * H_ * S_ * D_;

    static bool attrs_set = false;
    if (!attrs_set) {
        cudaFuncSetAttribute(scores_mma_kernel, cudaFuncAttributeMaxDynamicSharedMemorySize, SM_BYTES_S);
        cudaFuncSetAttribute(context_mma_kernel, cudaFuncAttributeMaxDynamicSharedMemorySize, SM_BYTES_C);
        attrs_set = true;
    }

    vt_kernel<<<dim3(S_ / 32, D_ / 32, B_ * H_), 256>>>(V);
    qk_prep_kernel<<<8192, 256>>>(Q, K);

    dim3 g1(S_ / 128, S_ / 128, B_ * H_);
    scores_mma_kernel<<<g1, 256, SM_BYTES_S>>>(mask, attn);

    softmax_kernel<<<B_ * H_ * S_, 256>>>(attn);

    dim3 g3(S_ / 128, B_ * H_);
    context_mma_kernel<<<g3, 256, SM_BYTES_C>>>(attn, ctx);

    (void)in_sizes; (void)n_in; (void)out_size;
}

// round 15
// speedup vs baseline: 1.4105x; 1.2090x over previous
#include <cuda_runtime.h>
#include <cuda_fp16.h>
#include <cstdint>

#define B_ 2
#define H_ 16
#define S_ 2048
#define D_ 128
#define SCALE 0.08838834764831845f   // 1/sqrt(128)
#define NEG (-1e9f)

// ctx kernel chunking
#define CW 72                        // 64 data + 8 pad (fp16 elems)
#define CH_ELEMS (128 * CW)
#define SM_BYTES_C (4 * CH_ELEMS * 2)   // Phi,Plo + V x2 stages = 73728 B

// scores kernel chunking (32-wide, double-buffered, cp.async direct)
#define CWS 40                       // 32 data + 8 pad
#define CHS_ELEMS (128 * CWS)        // 5120
#define SM_BYTES_S 67584             // max(2 stages x 3 tiles = 61440, staging 67584)

#define SGW 132                      // fp32 staging row stride (floats)

// Pre-converted operands in global memory (fp16)
__device__ __align__(16) __half g_Vt[(size_t)32 * 128 * 2048];    // V transposed, single fp16
__device__ __align__(16) __half g_QHi[(size_t)32 * 2048 * 128];   // Q split hi
__device__ __align__(16) __half g_QLo[(size_t)32 * 2048 * 128];   // Q split lo
__device__ __align__(16) __half g_KHat[(size_t)32 * 2048 * 128];  // K single fp16

// ---------------------------------------------------------------------------
__device__ __forceinline__ void mma_fp16(float* d,
                                         uint32_t a0, uint32_t a1, uint32_t a2, uint32_t a3,
                                         uint32_t b0, uint32_t b1) {
    asm volatile(
        "mma.sync.aligned.m16n8k16.row.col.f32.f16.f16.f32 "
        "{%0,%1,%2,%3}, {%4,%5,%6,%7}, {%8,%9}, {%0,%1,%2,%3};"
        : "+f"(d[0]), "+f"(d[1]), "+f"(d[2]), "+f"(d[3])
        : "r"(a0), "r"(a1), "r"(a2), "r"(a3), "r"(b0), "r"(b1));
}

__device__ __forceinline__ void ldm_x4(uint32_t& r0, uint32_t& r1, uint32_t& r2, uint32_t& r3,
                                       uint32_t addr) {
    asm volatile("ldmatrix.sync.aligned.m8n8.x4.shared.b16 {%0,%1,%2,%3}, [%4];"
                 : "=r"(r0), "=r"(r1), "=r"(r2), "=r"(r3) : "r"(addr));
}

__device__ __forceinline__ uint32_t smem_u32(const void* p) {
    return (uint32_t)__cvta_generic_to_shared(p);
}

__device__ __forceinline__ void cp_async16(uint32_t dst, const void* src) {
    asm volatile("cp.async.cg.shared.global [%0], [%1], 16;" :: "r"(dst), "l"(src));
}
#define CP_COMMIT() asm volatile("cp.async.commit_group;" ::: "memory")
#define CP_WAIT(n)  asm volatile("cp.async.wait_group %0;" :: "n"(n) : "memory")

__device__ __forceinline__ uint32_t pack2h(__half a, __half b) {
    return (uint32_t)__half_as_ushort(a) | ((uint32_t)__half_as_ushort(b) << 16);
}

// fp16 split of fp32x4: hi = rn(x), lo = rn(x - hi)
__device__ __forceinline__ void split4h(float4 v, uint2& hp, uint2& lp) {
    __half h0 = __float2half_rn(v.x), h1 = __float2half_rn(v.y);
    __half h2 = __float2half_rn(v.z), h3 = __float2half_rn(v.w);
    __half l0 = __float2half_rn(v.x - __half2float(h0));
    __half l1 = __float2half_rn(v.y - __half2float(h1));
    __half l2 = __float2half_rn(v.z - __half2float(h2));
    __half l3 = __float2half_rn(v.w - __half2float(h3));
    hp.x = pack2h(h0, h1); hp.y = pack2h(h2, h3);
    lp.x = pack2h(l0, l1); lp.y = pack2h(l2, l3);
}

__device__ __forceinline__ uint2 cvt4h(float4 v) {
    uint2 p;
    p.x = pack2h(__float2half_rn(v.x), __float2half_rn(v.y));
    p.y = pack2h(__float2half_rn(v.z), __float2half_rn(v.w));
    return p;
}

__device__ __forceinline__ void store_hilo4(__half* hi, __half* lo, uint32_t off, float4 v) {
    uint2 hp, lp;
    split4h(v, hp, lp);
    *(uint2*)(hi + off) = hp;
    *(uint2*)(lo + off) = lp;
}

__device__ __forceinline__ float warpRedMax(float v) {
    #pragma unroll
    for (int o = 16; o > 0; o >>= 1) v = fmaxf(v, __shfl_xor_sync(0xffffffffu, v, o));
    return v;
}
__device__ __forceinline__ float warpRedSum(float v) {
    #pragma unroll
    for (int o = 16; o > 0; o >>= 1) v += __shfl_xor_sync(0xffffffffu, v, o);
    return v;
}

// ---------------------------------------------------------------------------
// MMA over a chunk. Warp tile = 32 (M) x 64 (N): acc[2][8][4].
// A split hi/lo (2 MMA components), B single fp16.
// ---------------------------------------------------------------------------
template<int CWE, int KSTEPS>
__device__ __forceinline__ void mma_chunk_t(float acc[2][8][4],
                                            uint32_t aHi, uint32_t aLo, uint32_t bS) {
    #pragma unroll
    for (int ks = 0; ks < KSTEPS; ++ks) {
        const uint32_t kb = ks * 32;   // 16 fp16 = 32 bytes
        uint32_t ah[2][4], al[2][4];
        #pragma unroll
        for (int s = 0; s < 2; ++s) {
            const uint32_t so = (uint32_t)s * (16 * CWE * 2);
            ldm_x4(ah[s][0], ah[s][1], ah[s][2], ah[s][3], aHi + so + kb);
            ldm_x4(al[s][0], al[s][1], al[s][2], al[s][3], aLo + so + kb);
        }
        #pragma unroll
        for (int np = 0; np < 4; ++np) {   // 16 B rows = 2 n8-tiles
            const uint32_t bo = (uint32_t)np * (16 * CWE * 2) + kb;
            uint32_t b0, b1, b2, b3;
            ldm_x4(b0, b1, b2, b3, bS + bo);
            #pragma unroll
            for (int s = 0; s < 2; ++s) {
                mma_fp16(acc[s][2*np],     ah[s][0], ah[s][1], ah[s][2], ah[s][3], b0, b1);
                mma_fp16(acc[s][2*np],     al[s][0], al[s][1], al[s][2], al[s][3], b0, b1);
                mma_fp16(acc[s][2*np + 1], ah[s][0], ah[s][1], ah[s][2], ah[s][3], b2, b3);
                mma_fp16(acc[s][2*np + 1], al[s][0], al[s][1], al[s][2], al[s][3], b2, b3);
            }
        }
    }
}

// ---------------------------------------------------------------------------
// K0a: V -> Vt (transposed) single fp16
// ---------------------------------------------------------------------------
__global__ __launch_bounds__(256) void vt_kernel(const float* __restrict__ V) {
    __shared__ float t[32][33];
    const int k0 = blockIdx.x * 32, n0 = blockIdx.y * 32, bh = blockIdx.z;
    const int tid = threadIdx.x, c = tid & 31, r0 = tid >> 5;
    const float* Vb = V + (size_t)bh * S_ * D_;
    #pragma unroll
    for (int rr = r0; rr < 32; rr += 8)
        t[rr][c] = Vb[(size_t)(k0 + rr) * D_ + n0 + c];
    __syncthreads();
    __half* Hb = g_Vt + (size_t)bh * D_ * S_;
    #pragma unroll
    for (int rr = r0; rr < 32; rr += 8)
        Hb[(size_t)(n0 + rr) * S_ + k0 + c] = __float2half_rn(t[c][rr]);
}

// ---------------------------------------------------------------------------
// K0b: Q -> hi/lo fp16, K -> single fp16 (natural layout)
// ---------------------------------------------------------------------------
__global__ __launch_bounds__(256) void qk_prep_kernel(
    const float* __restrict__ Q, const float* __restrict__ K)
{
    const size_t i4 = ((size_t)blockIdx.x * 256 + threadIdx.x) * 4;
    uint2 hp, lp;
    float4 q = *(const float4*)&Q[i4];
    split4h(q, hp, lp);
    *(uint2*)&g_QHi[i4] = hp;
    *(uint2*)&g_QLo[i4] = lp;
    float4 k = *(const float4*)&K[i4];
    *(uint2*)&g_KHat[i4] = cvt4h(k);
}

// ---------------------------------------------------------------------------
// K1: scores = Q K^T * scale + mask -> attn scratch. 128x128 tile per CTA.
// cp.async 32-wide k-chunks, double buffered. Warp tile 32x64.
// Stage layout: [Qhi][Qlo][Khat], each CHS_ELEMS.
// ---------------------------------------------------------------------------
__global__ __launch_bounds__(256, 2) void scores_mma_kernel(
    const int* __restrict__ mask, float* __restrict__ attn)
{
    const int bh = blockIdx.z, b = bh >> 4;
    const int i0 = blockIdx.y * 128, j0 = blockIdx.x * 128;
    const int tid = threadIdx.x;

    float* attnBase = attn + ((size_t)bh * S_ + i0) * S_ + j0;

    if (j0 + 128 <= (i0 * 4) / 5) {
        const float4 z = make_float4(0.f, 0.f, 0.f, 0.f);
        #pragma unroll
        for (int it = 0; it < 16; ++it) {
            int idx = it * 256 + tid;
            *(float4*)&attnBase[(size_t)(idx >> 5) * S_ + ((idx & 31) << 2)] = z;
        }
        return;
    }

    extern __shared__ __half sm[];
    const uint32_t smBase = smem_u32(sm);

    const __half* Qh = g_QHi + ((size_t)bh * S_ + i0) * D_;
    const __half* Ql = g_QLo + ((size_t)bh * S_ + i0) * D_;
    const __half* Kh = g_KHat + ((size_t)bh * S_ + j0) * D_;

    const int lane = tid & 31, warp = tid >> 5;
    const int g = lane >> 2, c = lane & 3;
    const int mb2 = warp & 3;        // M block of 32 rows
    const int nb  = warp >> 2;       // N block of 64 cols

    float acc[2][8][4];
    #pragma unroll
    for (int s = 0; s < 2; ++s)
        #pragma unroll
        for (int nt = 0; nt < 8; ++nt)
            #pragma unroll
            for (int q = 0; q < 4; ++q) acc[s][nt][q] = 0.0f;

    const uint32_t aRowOff = ((mb2 * 32 + (lane & 15)) * CWS + (lane >> 4) * 8) * 2;
    const uint32_t bRowOff = ((nb * 64 + ((lane >> 4) << 3) + (lane & 7)) * CWS
                              + ((lane >> 3) & 1) * 8) * 2;

    const int cpRow = tid >> 1;
    const int cpE = (tid & 1) * 16;
    const uint32_t cpDst = (uint32_t)(cpRow * CWS + cpE) * 2;

    auto issue = [&](int ch, int st) {
        const int kc = ch * 32;
        const uint32_t sb = smBase + (uint32_t)st * (3 * CHS_ELEMS * 2);
        const size_t so = (size_t)cpRow * D_ + kc + cpE;
        cp_async16(sb + cpDst,                          Qh + so);
        cp_async16(sb + cpDst + 16,                     Qh + so + 8);
        cp_async16(sb + CHS_ELEMS * 2 + cpDst,          Ql + so);
        cp_async16(sb + CHS_ELEMS * 2 + cpDst + 16,     Ql + so + 8);
        cp_async16(sb + 2 * CHS_ELEMS * 2 + cpDst,      Kh + so);
        cp_async16(sb + 2 * CHS_ELEMS * 2 + cpDst + 16, Kh + so + 8);
    };

    issue(0, 0);
    CP_COMMIT();

    #pragma unroll
    for (int ch = 0; ch < 4; ++ch) {
        CP_WAIT(0);
        __syncthreads();
        if (ch < 3) {
            issue(ch + 1, (ch + 1) & 1);
            CP_COMMIT();
        }
        const uint32_t sb = smBase + (uint32_t)(ch & 1) * (3 * CHS_ELEMS * 2);
        mma_chunk_t<CWS, 2>(acc,
                            sb + aRowOff,
                            sb + CHS_ELEMS * 2 + aRowOff,
                            sb + 2 * CHS_ELEMS * 2 + bRowOff);
    }
    __syncthreads();   // reuse smem as fp32 staging

    float* stg = (float*)sm;
    #pragma unroll
    for (int s = 0; s < 2; ++s) {
        int r0 = mb2 * 32 + s * 16 + g;
        #pragma unroll
        for (int nt = 0; nt < 8; ++nt) {
            int cc = nb * 64 + nt * 8 + 2 * c;
            *(float2*)&stg[r0 * SGW + cc]       = make_float2(acc[s][nt][0], acc[s][nt][1]);
            *(float2*)&stg[(r0 + 8) * SGW + cc] = make_float2(acc[s][nt][2], acc[s][nt][3]);
        }
    }
    __syncthreads();

    const int* mB = mask + (size_t)b * S_ * S_;
    #pragma unroll
    for (int it = 0; it < 16; ++it) {
        int idx = it * 256 + tid;
        int r = idx >> 5, cc = (idx & 31) * 4;
        int i = i0 + r, thr = (i * 4) / 5, j = j0 + cc;
        int4 mv = *(const int4*)&mB[(size_t)i * S_ + j];
        float4 s = *(float4*)&stg[r * SGW + cc];
        float4 v;
        v.x = (mv.x || (j + 0) < thr) ? NEG : s.x * SCALE;
        v.y = (mv.y || (j + 1) < thr) ? NEG : s.y * SCALE;
        v.z = (mv.z || (j + 2) < thr) ? NEG : s.z * SCALE;
        v.w = (mv.w || (j + 3) < thr) ? NEG : s.w * SCALE;
        *(float4*)&attnBase[(size_t)r * S_ + cc] = v;
    }
}

// ---------------------------------------------------------------------------
// K2: row softmax over [jStart, S) only. [0, jStart) already holds final zeros.
// ---------------------------------------------------------------------------
__global__ __launch_bounds__(256) void softmax_kernel(float* __restrict__ attn)
{
    const int row = blockIdx.x;
    const int i = row & (S_ - 1);
    const int i0 = i & ~127;
    const int jStart = (((i0 * 4) / 5) >> 7) << 7;
    float* p = attn + (size_t)row * S_;
    const int tid = threadIdx.x;

    const int n4 = (S_ - jStart) >> 2;
    float4* p4 = (float4*)(p + jStart);
    const bool val0 = tid < n4;
    const bool val1 = tid + 256 < n4;

    float4 v0 = make_float4(NEG, NEG, NEG, NEG);
    float4 v1 = make_float4(NEG, NEG, NEG, NEG);
    if (val0) v0 = p4[tid];
    if (val1) v1 = p4[tid + 256];

    __shared__ float red[8];

    float m = fmaxf(fmaxf(fmaxf(v0.x, v0.y), fmaxf(v0.z, v0.w)),
                    fmaxf(fmaxf(v1.x, v1.y), fmaxf(v1.z, v1.w)));
    m = warpRedMax(m);
    if ((tid & 31) == 0) red[tid >> 5] = m;
    __syncthreads();
    float bm = red[0];
    #pragma unroll
    for (int k = 1; k < 8; ++k) bm = fmaxf(bm, red[k]);
    __syncthreads();

    v0.x = __expf(v0.x - bm); v0.y = __expf(v0.y - bm);
    v0.z = __expf(v0.z - bm); v0.w = __expf(v0.w - bm);
    v1.x = __expf(v1.x - bm); v1.y = __expf(v1.y - bm);
    v1.z = __expf(v1.z - bm); v1.w = __expf(v1.w - bm);

    float s = 0.0f;
    if (val0) s += (v0.x + v0.y) + (v0.z + v0.w);
    if (val1) s += (v1.x + v1.y) + (v1.z + v1.w);
    s = warpRedSum(s);
    if ((tid & 31) == 0) red[tid >> 5] = s;
    __syncthreads();
    float bs = 0.0f;
    #pragma unroll
    for (int k = 0; k < 8; ++k) bs += red[k];

    const float inv = 1.0f / bs;
    if (val0) {
        v0.x *= inv; v0.y *= inv; v0.z *= inv; v0.w *= inv;
        p4[tid] = v0;
    }
    if (val1) {
        v1.x *= inv; v1.y *= inv; v1.z *= inv; v1.w *= inv;
        p4[tid + 256] = v1;
    }
}

// ---------------------------------------------------------------------------
// K3: context = attn @ V. 128x128 output per CTA. Warp tile 32x64.
// P split fp16 (single buffer); V single fp16, double-buffered via cp.async.
// Layout: [Phi][Plo][V stage0][V stage1], each CH_ELEMS.
// ---------------------------------------------------------------------------
__global__ __launch_bounds__(256, 2) void context_mma_kernel(
    const float* __restrict__ attn, float* __restrict__ ctx)
{
    const int i0 = blockIdx.x * 128, bh = blockIdx.y;
    const int tid = threadIdx.x;

    extern __shared__ __half sm[];
    __half* Phi = sm;
    __half* Plo = sm + CH_ELEMS;
    __half* Vst = sm + 2 * CH_ELEMS;

    const float* Pb = attn + ((size_t)bh * S_ + i0) * S_;
    const __half* Vt = g_Vt + (size_t)bh * D_ * S_;

    const int lane = tid & 31, warp = tid >> 5;
    const int g = lane >> 2, c = lane & 3;
    const int mb2 = warp & 3;
    const int nb  = warp >> 2;

    float acc[2][8][4];
    #pragma unroll
    for (int s = 0; s < 2; ++s)
        #pragma unroll
        for (int nt = 0; nt < 8; ++nt)
            #pragma unroll
            for (int q = 0; q < 4; ++q) acc[s][nt][q] = 0.0f;

    const uint32_t aRowOff = ((mb2 * 32 + (lane & 15)) * CW + (lane >> 4) * 8) * 2;
    const uint32_t bRowOff = ((nb * 64 + ((lane >> 4) << 3) + (lane & 7)) * CW
                              + ((lane >> 3) & 1) * 8) * 2;
    const uint32_t aHiA = smem_u32(Phi) + aRowOff;
    const uint32_t aLoA = smem_u32(Plo) + aRowOff;
    const uint32_t vBase = smem_u32(Vst);
    const uint32_t bA0 = vBase + bRowOff;

    const int vn = tid >> 3, vk8 = (tid & 7) << 3;

    const int ch0 = (((i0 * 4) / 5) >> 7) * 2;

    {
        const int k0g = ch0 * 64;
        const uint32_t st = (uint32_t)(ch0 & 1) * (CH_ELEMS * 2);
        #pragma unroll
        for (int it = 0; it < 4; ++it) {
            int n = vn + it * 32;
            cp_async16(vBase + st + (uint32_t)(n * CW + vk8) * 2, &Vt[(size_t)n * S_ + k0g + vk8]);
        }
        CP_COMMIT();
    }

    for (int ch = ch0; ch < 32; ++ch) {
        if (ch > ch0) __syncthreads();
        const int k0g = ch * 64;
        #pragma unroll
        for (int it = 0; it < 8; ++it) {
            int idx = it * 256 + tid;
            int row = idx >> 4, c4 = (idx & 15) << 2;
            store_hilo4(Phi, Plo, row * CW + c4,
                        *(const float4*)&Pb[(size_t)row * S_ + k0g + c4]);
        }
        if (ch + 1 < 32) {
            const int k1g = (ch + 1) * 64;
            const uint32_t st = (uint32_t)((ch + 1) & 1) * (CH_ELEMS * 2);
            #pragma unroll
            for (int it = 0; it < 4; ++it) {
                int n = vn + it * 32;
                cp_async16(vBase + st + (uint32_t)(n * CW + vk8) * 2, &Vt[(size_t)n * S_ + k1g + vk8]);
            }
            CP_COMMIT();
            CP_WAIT(1);
        } else {
            CP_WAIT(0);
        }
        __syncthreads();
        const uint32_t st = (uint32_t)(ch & 1) * (CH_ELEMS * 2);
        mma_chunk_t<CW, 4>(acc, aHiA, aLoA, bA0 + st);
    }
    __syncthreads();

    float* stg = (float*)sm;
    #pragma unroll
    for (int s = 0; s < 2; ++s) {
        int r0 = mb2 * 32 + s * 16 + g;
        #pragma unroll
        for (int nt = 0; nt < 8; ++nt) {
            int cc = nb * 64 + nt * 8 + 2 * c;
            *(float2*)&stg[r0 * SGW + cc]       = make_float2(acc[s][nt][0], acc[s][nt][1]);
            *(float2*)&stg[(r0 + 8) * SGW + cc] = make_float2(acc[s][nt][2], acc[s][nt][3]);
        }
    }
    __syncthreads();

    #pragma unroll
    for (int it = 0; it < 16; ++it) {
        int idx = it * 256 + tid;
        int r = idx >> 5, c4 = (idx & 31) << 2;
        *(float4*)&ctx[((size_t)bh * S_ + i0 + r) * D_ + c4] = *(float4*)&stg[r * SGW + c4];
    }
}

// ---------------------------------------------------------------------------
// kernel_launch
// ---------------------------------------------------------------------------
extern "C" void kernel_launch(void* const* d_in, const int* in_sizes, int n_in,
                              void* d_out, int out_size)
{
    const float* Q    = (const float*)d_in[0];
    const float* K    = (const float*)d_in[1];
    const float* V    = (const float*)d_in[2];
    const int*   mask = (const int*)d_in[3];

    float* out  = (float*)d_out;
    float* ctx  = out;
    float* attn = out + (size_t)B_ * H_ * S_ * D_;

    static bool attrs_set = false;
    if (!attrs_set) {
        cudaFuncSetAttribute(scores_mma_kernel, cudaFuncAttributeMaxDynamicSharedMemorySize, SM_BYTES_S);
        cudaFuncSetAttribute(context_mma_kernel, cudaFuncAttributeMaxDynamicSharedMemorySize, SM_BYTES_C);
        attrs_set = true;
    }

    vt_kernel<<<dim3(S_ / 32, D_ / 32, B_ * H_), 256>>>(V);
    qk_prep_kernel<<<8192, 256>>>(Q, K);

    dim3 g1(S_ / 128, S_ / 128, B_ * H_);
    scores_mma_kernel<<<g1, 256, SM_BYTES_S>>>(mask, attn);

    softmax_kernel<<<B_ * H_ * S_, 256>>>(attn);

    dim3 g3(S_ / 128, B_ * H_);
    context_mma_kernel<<<g3, 256, SM_BYTES_C>>>(attn, ctx);

    (void)in_sizes; (void)n_in; (void)out_size;
}

// round 16
// speedup vs baseline: 1.7480x; 1.2392x over previous
#include <cuda_runtime.h>
#include <cuda_fp16.h>
#include <cstdint>

#define B_ 2
#define H_ 16
#define S_ 2048
#define D_ 128
#define SCALE 0.08838834764831845f   // 1/sqrt(128)
#define NEG (-1e9f)

// ctx kernel chunking
#define CW 72                        // 64 data + 8 pad (fp16 elems)
#define CH_ELEMS (128 * CW)
#define SM_BYTES_C 67584             // max(Phat + V x2 stages = 55296, staging 67584)

// scores kernel chunking (32-wide, double-buffered, cp.async direct)
#define CWS 40                       // 32 data + 8 pad
#define CHS_ELEMS (128 * CWS)        // 5120
#define SM_BYTES_S 67584             // max(2 stages x 2 tiles = 40960, staging 67584)

#define SGW 132                      // fp32 staging row stride (floats)

// Pre-converted operands in global memory (single-rounded fp16)
__device__ __align__(16) __half g_Vt[(size_t)32 * 128 * 2048];    // V transposed
__device__ __align__(16) __half g_QHat[(size_t)32 * 2048 * 128];
__device__ __align__(16) __half g_KHat[(size_t)32 * 2048 * 128];

// ---------------------------------------------------------------------------
__device__ __forceinline__ void mma_fp16(float* d,
                                         uint32_t a0, uint32_t a1, uint32_t a2, uint32_t a3,
                                         uint32_t b0, uint32_t b1) {
    asm volatile(
        "mma.sync.aligned.m16n8k16.row.col.f32.f16.f16.f32 "
        "{%0,%1,%2,%3}, {%4,%5,%6,%7}, {%8,%9}, {%0,%1,%2,%3};"
        : "+f"(d[0]), "+f"(d[1]), "+f"(d[2]), "+f"(d[3])
        : "r"(a0), "r"(a1), "r"(a2), "r"(a3), "r"(b0), "r"(b1));
}

__device__ __forceinline__ void ldm_x4(uint32_t& r0, uint32_t& r1, uint32_t& r2, uint32_t& r3,
                                       uint32_t addr) {
    asm volatile("ldmatrix.sync.aligned.m8n8.x4.shared.b16 {%0,%1,%2,%3}, [%4];"
                 : "=r"(r0), "=r"(r1), "=r"(r2), "=r"(r3) : "r"(addr));
}

__device__ __forceinline__ uint32_t smem_u32(const void* p) {
    return (uint32_t)__cvta_generic_to_shared(p);
}

__device__ __forceinline__ void cp_async16(uint32_t dst, const void* src) {
    asm volatile("cp.async.cg.shared.global [%0], [%1], 16;" :: "r"(dst), "l"(src));
}
#define CP_COMMIT() asm volatile("cp.async.commit_group;" ::: "memory")
#define CP_WAIT(n)  asm volatile("cp.async.wait_group %0;" :: "n"(n) : "memory")

__device__ __forceinline__ uint32_t pack2h(__half a, __half b) {
    return (uint32_t)__half_as_ushort(a) | ((uint32_t)__half_as_ushort(b) << 16);
}

__device__ __forceinline__ uint2 cvt4h(float4 v) {
    uint2 p;
    p.x = pack2h(__float2half_rn(v.x), __float2half_rn(v.y));
    p.y = pack2h(__float2half_rn(v.z), __float2half_rn(v.w));
    return p;
}

__device__ __forceinline__ float warpRedMax(float v) {
    #pragma unroll
    for (int o = 16; o > 0; o >>= 1) v = fmaxf(v, __shfl_xor_sync(0xffffffffu, v, o));
    return v;
}
__device__ __forceinline__ float warpRedSum(float v) {
    #pragma unroll
    for (int o = 16; o > 0; o >>= 1) v += __shfl_xor_sync(0xffffffffu, v, o);
    return v;
}

// ---------------------------------------------------------------------------
// MMA over a chunk. Warp tile = 32 (M) x 64 (N): acc[2][8][4].
// Single fp16 A, single fp16 B (plain fp16 GEMM).
// ---------------------------------------------------------------------------
template<int CWE, int KSTEPS>
__device__ __forceinline__ void mma_chunk_t(float acc[2][8][4],
                                            uint32_t aS, uint32_t bS) {
    #pragma unroll
    for (int ks = 0; ks < KSTEPS; ++ks) {
        const uint32_t kb = ks * 32;   // 16 fp16 = 32 bytes
        uint32_t a[2][4];
        #pragma unroll
        for (int s = 0; s < 2; ++s) {
            const uint32_t so = (uint32_t)s * (16 * CWE * 2);
            ldm_x4(a[s][0], a[s][1], a[s][2], a[s][3], aS + so + kb);
        }
        #pragma unroll
        for (int np = 0; np < 4; ++np) {   // 16 B rows = 2 n8-tiles
            const uint32_t bo = (uint32_t)np * (16 * CWE * 2) + kb;
            uint32_t b0, b1, b2, b3;
            ldm_x4(b0, b1, b2, b3, bS + bo);
            #pragma unroll
            for (int s = 0; s < 2; ++s) {
                mma_fp16(acc[s][2*np],     a[s][0], a[s][1], a[s][2], a[s][3], b0, b1);
                mma_fp16(acc[s][2*np + 1], a[s][0], a[s][1], a[s][2], a[s][3], b2, b3);
            }
        }
    }
}

// ---------------------------------------------------------------------------
// K0a: V -> Vt (transposed) single fp16
// ---------------------------------------------------------------------------
__global__ __launch_bounds__(256) void vt_kernel(const float* __restrict__ V) {
    __shared__ float t[32][33];
    const int k0 = blockIdx.x * 32, n0 = blockIdx.y * 32, bh = blockIdx.z;
    const int tid = threadIdx.x, c = tid & 31, r0 = tid >> 5;
    const float* Vb = V + (size_t)bh * S_ * D_;
    #pragma unroll
    for (int rr = r0; rr < 32; rr += 8)
        t[rr][c] = Vb[(size_t)(k0 + rr) * D_ + n0 + c];
    __syncthreads();
    __half* Hb = g_Vt + (size_t)bh * D_ * S_;
    #pragma unroll
    for (int rr = r0; rr < 32; rr += 8)
        Hb[(size_t)(n0 + rr) * S_ + k0 + c] = __float2half_rn(t[c][rr]);
}

// ---------------------------------------------------------------------------
// K0b: Q,K -> single fp16 (natural layout)
// ---------------------------------------------------------------------------
__global__ __launch_bounds__(256) void qk_prep_kernel(
    const float* __restrict__ Q, const float* __restrict__ K)
{
    const size_t i4 = ((size_t)blockIdx.x * 256 + threadIdx.x) * 4;
    *(uint2*)&g_QHat[i4] = cvt4h(*(const float4*)&Q[i4]);
    *(uint2*)&g_KHat[i4] = cvt4h(*(const float4*)&K[i4]);
}

// ---------------------------------------------------------------------------
// K1: scores = Q K^T * scale + mask -> attn scratch. 128x128 tile per CTA.
// cp.async 32-wide k-chunks, double buffered. Warp tile 32x64.
// Stage layout: [Qhat][Khat], each CHS_ELEMS.
// ---------------------------------------------------------------------------
__global__ __launch_bounds__(256, 2) void scores_mma_kernel(
    const int* __restrict__ mask, float* __restrict__ attn)
{
    const int bh = blockIdx.z, b = bh >> 4;
    const int i0 = blockIdx.y * 128, j0 = blockIdx.x * 128;
    const int tid = threadIdx.x;

    float* attnBase = attn + ((size_t)bh * S_ + i0) * S_ + j0;

    if (j0 + 128 <= (i0 * 4) / 5) {
        const float4 z = make_float4(0.f, 0.f, 0.f, 0.f);
        #pragma unroll
        for (int it = 0; it < 16; ++it) {
            int idx = it * 256 + tid;
            *(float4*)&attnBase[(size_t)(idx >> 5) * S_ + ((idx & 31) << 2)] = z;
        }
        return;
    }

    extern __shared__ __half sm[];
    const uint32_t smBase = smem_u32(sm);

    const __half* Qh = g_QHat + ((size_t)bh * S_ + i0) * D_;
    const __half* Kh = g_KHat + ((size_t)bh * S_ + j0) * D_;

    const int lane = tid & 31, warp = tid >> 5;
    const int g = lane >> 2, c = lane & 3;
    const int mb2 = warp & 3;        // M block of 32 rows
    const int nb  = warp >> 2;       // N block of 64 cols

    float acc[2][8][4];
    #pragma unroll
    for (int s = 0; s < 2; ++s)
        #pragma unroll
        for (int nt = 0; nt < 8; ++nt)
            #pragma unroll
            for (int q = 0; q < 4; ++q) acc[s][nt][q] = 0.0f;

    const uint32_t aRowOff = ((mb2 * 32 + (lane & 15)) * CWS + (lane >> 4) * 8) * 2;
    const uint32_t bRowOff = ((nb * 64 + ((lane >> 4) << 3) + (lane & 7)) * CWS
                              + ((lane >> 3) & 1) * 8) * 2;

    const int cpRow = tid >> 1;
    const int cpE = (tid & 1) * 16;
    const uint32_t cpDst = (uint32_t)(cpRow * CWS + cpE) * 2;

    auto issue = [&](int ch, int st) {
        const int kc = ch * 32;
        const uint32_t sb = smBase + (uint32_t)st * (2 * CHS_ELEMS * 2);
        const size_t so = (size_t)cpRow * D_ + kc + cpE;
        cp_async16(sb + cpDst,                      Qh + so);
        cp_async16(sb + cpDst + 16,                 Qh + so + 8);
        cp_async16(sb + CHS_ELEMS * 2 + cpDst,      Kh + so);
        cp_async16(sb + CHS_ELEMS * 2 + cpDst + 16, Kh + so + 8);
    };

    issue(0, 0);
    CP_COMMIT();

    #pragma unroll
    for (int ch = 0; ch < 4; ++ch) {
        CP_WAIT(0);
        __syncthreads();
        if (ch < 3) {
            issue(ch + 1, (ch + 1) & 1);
            CP_COMMIT();
        }
        const uint32_t sb = smBase + (uint32_t)(ch & 1) * (2 * CHS_ELEMS * 2);
        mma_chunk_t<CWS, 2>(acc,
                            sb + aRowOff,
                            sb + CHS_ELEMS * 2 + bRowOff);
    }
    __syncthreads();   // reuse smem as fp32 staging

    float* stg = (float*)sm;
    #pragma unroll
    for (int s = 0; s < 2; ++s) {
        int r0 = mb2 * 32 + s * 16 + g;
        #pragma unroll
        for (int nt = 0; nt < 8; ++nt) {
            int cc = nb * 64 + nt * 8 + 2 * c;
            *(float2*)&stg[r0 * SGW + cc]       = make_float2(acc[s][nt][0], acc[s][nt][1]);
            *(float2*)&stg[(r0 + 8) * SGW + cc] = make_float2(acc[s][nt][2], acc[s][nt][3]);
        }
    }
    __syncthreads();

    const int* mB = mask + (size_t)b * S_ * S_;
    #pragma unroll
    for (int it = 0; it < 16; ++it) {
        int idx = it * 256 + tid;
        int r = idx >> 5, cc = (idx & 31) * 4;
        int i = i0 + r, thr = (i * 4) / 5, j = j0 + cc;
        int4 mv = *(const int4*)&mB[(size_t)i * S_ + j];
        float4 s = *(float4*)&stg[r * SGW + cc];
        float4 v;
        v.x = (mv.x || (j + 0) < thr) ? NEG : s.x * SCALE;
        v.y = (mv.y || (j + 1) < thr) ? NEG : s.y * SCALE;
        v.z = (mv.z || (j + 2) < thr) ? NEG : s.z * SCALE;
        v.w = (mv.w || (j + 3) < thr) ? NEG : s.w * SCALE;
        *(float4*)&attnBase[(size_t)r * S_ + cc] = v;
    }
}

// ---------------------------------------------------------------------------
// K2: row softmax over [jStart, S) only. [0, jStart) already holds final zeros.
// ---------------------------------------------------------------------------
__global__ __launch_bounds__(256) void softmax_kernel(float* __restrict__ attn)
{
    const int row = blockIdx.x;
    const int i = row & (S_ - 1);
    const int i0 = i & ~127;
    const int jStart = (((i0 * 4) / 5) >> 7) << 7;
    float* p = attn + (size_t)row * S_;
    const int tid = threadIdx.x;

    const int n4 = (S_ - jStart) >> 2;
    float4* p4 = (float4*)(p + jStart);
    const bool val0 = tid < n4;
    const bool val1 = tid + 256 < n4;

    float4 v0 = make_float4(NEG, NEG, NEG, NEG);
    float4 v1 = make_float4(NEG, NEG, NEG, NEG);
    if (val0) v0 = p4[tid];
    if (val1) v1 = p4[tid + 256];

    __shared__ float red[8];

    float m = fmaxf(fmaxf(fmaxf(v0.x, v0.y), fmaxf(v0.z, v0.w)),
                    fmaxf(fmaxf(v1.x, v1.y), fmaxf(v1.z, v1.w)));
    m = warpRedMax(m);
    if ((tid & 31) == 0) red[tid >> 5] = m;
    __syncthreads();
    float bm = red[0];
    #pragma unroll
    for (int k = 1; k < 8; ++k) bm = fmaxf(bm, red[k]);
    __syncthreads();

    v0.x = __expf(v0.x - bm); v0.y = __expf(v0.y - bm);
    v0.z = __expf(v0.z - bm); v0.w = __expf(v0.w - bm);
    v1.x = __expf(v1.x - bm); v1.y = __expf(v1.y - bm);
    v1.z = __expf(v1.z - bm); v1.w = __expf(v1.w - bm);

    float s = 0.0f;
    if (val0) s += (v0.x + v0.y) + (v0.z + v0.w);
    if (val1) s += (v1.x + v1.y) + (v1.z + v1.w);
    s = warpRedSum(s);
    if ((tid & 31) == 0) red[tid >> 5] = s;
    __syncthreads();
    float bs = 0.0f;
    #pragma unroll
    for (int k = 0; k < 8; ++k) bs += red[k];

    const float inv = 1.0f / bs;
    if (val0) {
        v0.x *= inv; v0.y *= inv; v0.z *= inv; v0.w *= inv;
        p4[tid] = v0;
    }
    if (val1) {
        v1.x *= inv; v1.y *= inv; v1.z *= inv; v1.w *= inv;
        p4[tid + 256] = v1;
    }
}

// ---------------------------------------------------------------------------
// K3: context = attn @ V. 128x128 output per CTA. Warp tile 32x64.
// P single fp16 (single buffer); V single fp16, double-buffered via cp.async.
// Layout: [Phat][V stage0][V stage1], each CH_ELEMS.
// ---------------------------------------------------------------------------
__global__ __launch_bounds__(256, 2) void context_mma_kernel(
    const float* __restrict__ attn, float* __restrict__ ctx)
{
    const int i0 = blockIdx.x * 128, bh = blockIdx.y;
    const int tid = threadIdx.x;

    extern __shared__ __half sm[];
    __half* Pht = sm;
    __half* Vst = sm + CH_ELEMS;

    const float* Pb = attn + ((size_t)bh * S_ + i0) * S_;
    const __half* Vt = g_Vt + (size_t)bh * D_ * S_;

    const int lane = tid & 31, warp = tid >> 5;
    const int g = lane >> 2, c = lane & 3;
    const int mb2 = warp & 3;
    const int nb  = warp >> 2;

    float acc[2][8][4];
    #pragma unroll
    for (int s = 0; s < 2; ++s)
        #pragma unroll
        for (int nt = 0; nt < 8; ++nt)
            #pragma unroll
            for (int q = 0; q < 4; ++q) acc[s][nt][q] = 0.0f;

    const uint32_t aRowOff = ((mb2 * 32 + (lane & 15)) * CW + (lane >> 4) * 8) * 2;
    const uint32_t bRowOff = ((nb * 64 + ((lane >> 4) << 3) + (lane & 7)) * CW
                              + ((lane >> 3) & 1) * 8) * 2;
    const uint32_t aA = smem_u32(Pht) + aRowOff;
    const uint32_t vBase = smem_u32(Vst);
    const uint32_t bA0 = vBase + bRowOff;

    const int vn = tid >> 3, vk8 = (tid & 7) << 3;

    const int ch0 = (((i0 * 4) / 5) >> 7) * 2;

    {
        const int k0g = ch0 * 64;
        const uint32_t st = (uint32_t)(ch0 & 1) * (CH_ELEMS * 2);
        #pragma unroll
        for (int it = 0; it < 4; ++it) {
            int n = vn + it * 32;
            cp_async16(vBase + st + (uint32_t)(n * CW + vk8) * 2, &Vt[(size_t)n * S_ + k0g + vk8]);
        }
        CP_COMMIT();
    }

    for (int ch = ch0; ch < 32; ++ch) {
        if (ch > ch0) __syncthreads();
        const int k0g = ch * 64;
        #pragma unroll
        for (int it = 0; it < 8; ++it) {
            int idx = it * 256 + tid;
            int row = idx >> 4, c4 = (idx & 15) << 2;
            *(uint2*)(Pht + row * CW + c4) =
                cvt4h(*(const float4*)&Pb[(size_t)row * S_ + k0g + c4]);
        }
        if (ch + 1 < 32) {
            const int k1g = (ch + 1) * 64;
            const uint32_t st = (uint32_t)((ch + 1) & 1) * (CH_ELEMS * 2);
            #pragma unroll
            for (int it = 0; it < 4; ++it) {
                int n = vn + it * 32;
                cp_async16(vBase + st + (uint32_t)(n * CW + vk8) * 2, &Vt[(size_t)n * S_ + k1g + vk8]);
            }
            CP_COMMIT();
            CP_WAIT(1);
        } else {
            CP_WAIT(0);
        }
        __syncthreads();
        const uint32_t st = (uint32_t)(ch & 1) * (CH_ELEMS * 2);
        mma_chunk_t<CW, 4>(acc, aA, bA0 + st);
    }
    __syncthreads();

    float* stg = (float*)sm;
    #pragma unroll
    for (int s = 0; s < 2; ++s) {
        int r0 = mb2 * 32 + s * 16 + g;
        #pragma unroll
        for (int nt = 0; nt < 8; ++nt) {
            int cc = nb * 64 + nt * 8 + 2 * c;
            *(float2*)&stg[r0 * SGW + cc]       = make_float2(acc[s][nt][0], acc[s][nt][1]);
            *(float2*)&stg[(r0 + 8) * SGW + cc] = make_float2(acc[s][nt][2], acc[s][nt][3]);
        }
    }
    __syncthreads();

    #pragma unroll
    for (int it = 0; it < 16; ++it) {
        int idx = it * 256 + tid;
        int r = idx >> 5, c4 = (idx & 31) << 2;
        *(float4*)&ctx[((size_t)bh * S_ + i0 + r) * D_ + c4] = *(float4*)&stg[r * SGW + c4];
    }
}

// ---------------------------------------------------------------------------
// kernel_launch
// ---------------------------------------------------------------------------
extern "C" void kernel_launch(void* const* d_in, const int* in_sizes, int n_in,
                              void* d_out, int out_size)
{
    const float* Q    = (const float*)d_in[0];
    const float* K    = (const float*)d_in[1];
    const float* V    = (const float*)d_in[2];
    const int*   mask = (const int*)d_in[3];

    float* out  = (float*)d_out;
    float* ctx  = out;
    float* attn = out + (size_t)B_ * H_ * S_ * D_;

    static bool attrs_set = false;
    if (!attrs_set) {
        cudaFuncSetAttribute(scores_mma_kernel, cudaFuncAttributeMaxDynamicSharedMemorySize, SM_BYTES_S);
        cudaFuncSetAttribute(context_mma_kernel, cudaFuncAttributeMaxDynamicSharedMemorySize, SM_BYTES_C);
        attrs_set = true;
    }

    vt_kernel<<<dim3(S_ / 32, D_ / 32, B_ * H_), 256>>>(V);
    qk_prep_kernel<<<8192, 256>>>(Q, K);

    dim3 g1(S_ / 128, S_ / 128, B_ * H_);
    scores_mma_kernel<<<g1, 256, SM_BYTES_S>>>(mask, attn);

    softmax_kernel<<<B_ * H_ * S_, 256>>>(attn);

    dim3 g3(S_ / 128, B_ * H_);
    context_mma_kernel<<<g3, 256, SM_BYTES_C>>>(attn, ctx);

    (void)in_sizes; (void)n_in; (void)out_size;
}

// round 17
// speedup vs baseline: 1.7800x; 1.0183x over previous
#include <cuda_runtime.h>
#include <cuda_fp16.h>
#include <cstdint>

#define B_ 2
#define H_ 16
#define S_ 2048
#define D_ 128
#define SCALE 0.08838834764831845f   // 1/sqrt(128)
#define NEG (-1e9f)

// ctx kernel chunking
#define CW 72                        // 64 data + 8 pad (fp16 elems)
#define CH_ELEMS (128 * CW)
#define SM_BYTES_C 73728             // P x2 + V x2 stages (>= staging 67584)

// scores kernel chunking (32-wide, double-buffered, cp.async direct)
#define CWS 40                       // 32 data + 8 pad
#define CHS_ELEMS (128 * CWS)        // 5120
#define SM_BYTES_S 67584             // max(2 stages x 2 tiles = 40960, staging 67584)

#define SGW 132                      // fp32 staging row stride (floats)

// Pre-converted operands in global memory (single-rounded fp16)
__device__ __align__(16) __half g_Vt[(size_t)32 * 128 * 2048];    // V transposed
__device__ __align__(16) __half g_QHat[(size_t)32 * 2048 * 128];
__device__ __align__(16) __half g_KHat[(size_t)32 * 2048 * 128];
__device__ __align__(16) __half g_Phat[(size_t)32 * 2048 * 2048]; // fp16 probs (softmax out)

// ---------------------------------------------------------------------------
__device__ __forceinline__ void mma_fp16(float* d,
                                         uint32_t a0, uint32_t a1, uint32_t a2, uint32_t a3,
                                         uint32_t b0, uint32_t b1) {
    asm volatile(
        "mma.sync.aligned.m16n8k16.row.col.f32.f16.f16.f32 "
        "{%0,%1,%2,%3}, {%4,%5,%6,%7}, {%8,%9}, {%0,%1,%2,%3};"
        : "+f"(d[0]), "+f"(d[1]), "+f"(d[2]), "+f"(d[3])
        : "r"(a0), "r"(a1), "r"(a2), "r"(a3), "r"(b0), "r"(b1));
}

__device__ __forceinline__ void ldm_x4(uint32_t& r0, uint32_t& r1, uint32_t& r2, uint32_t& r3,
                                       uint32_t addr) {
    asm volatile("ldmatrix.sync.aligned.m8n8.x4.shared.b16 {%0,%1,%2,%3}, [%4];"
                 : "=r"(r0), "=r"(r1), "=r"(r2), "=r"(r3) : "r"(addr));
}

__device__ __forceinline__ uint32_t smem_u32(const void* p) {
    return (uint32_t)__cvta_generic_to_shared(p);
}

__device__ __forceinline__ void cp_async16(uint32_t dst, const void* src) {
    asm volatile("cp.async.cg.shared.global [%0], [%1], 16;" :: "r"(dst), "l"(src));
}
#define CP_COMMIT() asm volatile("cp.async.commit_group;" ::: "memory")
#define CP_WAIT(n)  asm volatile("cp.async.wait_group %0;" :: "n"(n) : "memory")

__device__ __forceinline__ uint32_t pack2h(__half a, __half b) {
    return (uint32_t)__half_as_ushort(a) | ((uint32_t)__half_as_ushort(b) << 16);
}

__device__ __forceinline__ uint2 cvt4h(float4 v) {
    uint2 p;
    p.x = pack2h(__float2half_rn(v.x), __float2half_rn(v.y));
    p.y = pack2h(__float2half_rn(v.z), __float2half_rn(v.w));
    return p;
}

__device__ __forceinline__ float warpRedMax(float v) {
    #pragma unroll
    for (int o = 16; o > 0; o >>= 1) v = fmaxf(v, __shfl_xor_sync(0xffffffffu, v, o));
    return v;
}
__device__ __forceinline__ float warpRedSum(float v) {
    #pragma unroll
    for (int o = 16; o > 0; o >>= 1) v += __shfl_xor_sync(0xffffffffu, v, o);
    return v;
}

// ---------------------------------------------------------------------------
// MMA over a chunk. Warp tile = 32 (M) x 64 (N): acc[2][8][4]. Plain fp16.
// ---------------------------------------------------------------------------
template<int CWE, int KSTEPS>
__device__ __forceinline__ void mma_chunk_t(float acc[2][8][4],
                                            uint32_t aS, uint32_t bS) {
    #pragma unroll
    for (int ks = 0; ks < KSTEPS; ++ks) {
        const uint32_t kb = ks * 32;   // 16 fp16 = 32 bytes
        uint32_t a[2][4];
        #pragma unroll
        for (int s = 0; s < 2; ++s) {
            const uint32_t so = (uint32_t)s * (16 * CWE * 2);
            ldm_x4(a[s][0], a[s][1], a[s][2], a[s][3], aS + so + kb);
        }
        #pragma unroll
        for (int np = 0; np < 4; ++np) {   // 16 B rows = 2 n8-tiles
            const uint32_t bo = (uint32_t)np * (16 * CWE * 2) + kb;
            uint32_t b0, b1, b2, b3;
            ldm_x4(b0, b1, b2, b3, bS + bo);
            #pragma unroll
            for (int s = 0; s < 2; ++s) {
                mma_fp16(acc[s][2*np],     a[s][0], a[s][1], a[s][2], a[s][3], b0, b1);
                mma_fp16(acc[s][2*np + 1], a[s][0], a[s][1], a[s][2], a[s][3], b2, b3);
            }
        }
    }
}

// ---------------------------------------------------------------------------
// K0a: V -> Vt (transposed) single fp16
// ---------------------------------------------------------------------------
__global__ __launch_bounds__(256) void vt_kernel(const float* __restrict__ V) {
    __shared__ float t[32][33];
    const int k0 = blockIdx.x * 32, n0 = blockIdx.y * 32, bh = blockIdx.z;
    const int tid = threadIdx.x, c = tid & 31, r0 = tid >> 5;
    const float* Vb = V + (size_t)bh * S_ * D_;
    #pragma unroll
    for (int rr = r0; rr < 32; rr += 8)
        t[rr][c] = Vb[(size_t)(k0 + rr) * D_ + n0 + c];
    __syncthreads();
    __half* Hb = g_Vt + (size_t)bh * D_ * S_;
    #pragma unroll
    for (int rr = r0; rr < 32; rr += 8)
        Hb[(size_t)(n0 + rr) * S_ + k0 + c] = __float2half_rn(t[c][rr]);
}

// ---------------------------------------------------------------------------
// K0b: Q,K -> single fp16 (natural layout)
// ---------------------------------------------------------------------------
__global__ __launch_bounds__(256) void qk_prep_kernel(
    const float* __restrict__ Q, const float* __restrict__ K)
{
    const size_t i4 = ((size_t)blockIdx.x * 256 + threadIdx.x) * 4;
    *(uint2*)&g_QHat[i4] = cvt4h(*(const float4*)&Q[i4]);
    *(uint2*)&g_KHat[i4] = cvt4h(*(const float4*)&K[i4]);
}

// ---------------------------------------------------------------------------
// K1: scores = Q K^T * scale + mask -> attn scratch. 128x128 tile per CTA.
// cp.async 32-wide k-chunks, double buffered. Warp tile 32x64.
// ---------------------------------------------------------------------------
__global__ __launch_bounds__(256, 2) void scores_mma_kernel(
    const int* __restrict__ mask, float* __restrict__ attn)
{
    const int bh = blockIdx.z, b = bh >> 4;
    const int i0 = blockIdx.y * 128, j0 = blockIdx.x * 128;
    const int tid = threadIdx.x;

    float* attnBase = attn + ((size_t)bh * S_ + i0) * S_ + j0;

    if (j0 + 128 <= (i0 * 4) / 5) {
        const float4 z = make_float4(0.f, 0.f, 0.f, 0.f);
        #pragma unroll
        for (int it = 0; it < 16; ++it) {
            int idx = it * 256 + tid;
            *(float4*)&attnBase[(size_t)(idx >> 5) * S_ + ((idx & 31) << 2)] = z;
        }
        return;
    }

    extern __shared__ __half sm[];
    const uint32_t smBase = smem_u32(sm);

    const __half* Qh = g_QHat + ((size_t)bh * S_ + i0) * D_;
    const __half* Kh = g_KHat + ((size_t)bh * S_ + j0) * D_;

    const int lane = tid & 31, warp = tid >> 5;
    const int g = lane >> 2, c = lane & 3;
    const int mb2 = warp & 3;        // M block of 32 rows
    const int nb  = warp >> 2;       // N block of 64 cols

    float acc[2][8][4];
    #pragma unroll
    for (int s = 0; s < 2; ++s)
        #pragma unroll
        for (int nt = 0; nt < 8; ++nt)
            #pragma unroll
            for (int q = 0; q < 4; ++q) acc[s][nt][q] = 0.0f;

    const uint32_t aRowOff = ((mb2 * 32 + (lane & 15)) * CWS + (lane >> 4) * 8) * 2;
    const uint32_t bRowOff = ((nb * 64 + ((lane >> 4) << 3) + (lane & 7)) * CWS
                              + ((lane >> 3) & 1) * 8) * 2;

    const int cpRow = tid >> 1;
    const int cpE = (tid & 1) * 16;
    const uint32_t cpDst = (uint32_t)(cpRow * CWS + cpE) * 2;

    auto issue = [&](int ch, int st) {
        const int kc = ch * 32;
        const uint32_t sb = smBase + (uint32_t)st * (2 * CHS_ELEMS * 2);
        const size_t so = (size_t)cpRow * D_ + kc + cpE;
        cp_async16(sb + cpDst,                      Qh + so);
        cp_async16(sb + cpDst + 16,                 Qh + so + 8);
        cp_async16(sb + CHS_ELEMS * 2 + cpDst,      Kh + so);
        cp_async16(sb + CHS_ELEMS * 2 + cpDst + 16, Kh + so + 8);
    };

    issue(0, 0);
    CP_COMMIT();

    #pragma unroll
    for (int ch = 0; ch < 4; ++ch) {
        CP_WAIT(0);
        __syncthreads();
        if (ch < 3) {
            issue(ch + 1, (ch + 1) & 1);
            CP_COMMIT();
        }
        const uint32_t sb = smBase + (uint32_t)(ch & 1) * (2 * CHS_ELEMS * 2);
        mma_chunk_t<CWS, 2>(acc,
                            sb + aRowOff,
                            sb + CHS_ELEMS * 2 + bRowOff);
    }
    __syncthreads();   // reuse smem as fp32 staging

    float* stg = (float*)sm;
    #pragma unroll
    for (int s = 0; s < 2; ++s) {
        int r0 = mb2 * 32 + s * 16 + g;
        #pragma unroll
        for (int nt = 0; nt < 8; ++nt) {
            int cc = nb * 64 + nt * 8 + 2 * c;
            *(float2*)&stg[r0 * SGW + cc]       = make_float2(acc[s][nt][0], acc[s][nt][1]);
            *(float2*)&stg[(r0 + 8) * SGW + cc] = make_float2(acc[s][nt][2], acc[s][nt][3]);
        }
    }
    __syncthreads();

    const int* mB = mask + (size_t)b * S_ * S_;
    #pragma unroll
    for (int it = 0; it < 16; ++it) {
        int idx = it * 256 + tid;
        int r = idx >> 5, cc = (idx & 31) * 4;
        int i = i0 + r, thr = (i * 4) / 5, j = j0 + cc;
        int4 mv = *(const int4*)&mB[(size_t)i * S_ + j];
        float4 s = *(float4*)&stg[r * SGW + cc];
        float4 v;
        v.x = (mv.x || (j + 0) < thr) ? NEG : s.x * SCALE;
        v.y = (mv.y || (j + 1) < thr) ? NEG : s.y * SCALE;
        v.z = (mv.z || (j + 2) < thr) ? NEG : s.z * SCALE;
        v.w = (mv.w || (j + 3) < thr) ? NEG : s.w * SCALE;
        *(float4*)&attnBase[(size_t)r * S_ + cc] = v;
    }
}

// ---------------------------------------------------------------------------
// K2: row softmax over [jStart, S); also writes fp16 P-hat scratch for ctx.
// [0, jStart) of attn already holds final zeros (scores window CTAs).
// ---------------------------------------------------------------------------
__global__ __launch_bounds__(256) void softmax_kernel(float* __restrict__ attn)
{
    const int row = blockIdx.x;
    const int i = row & (S_ - 1);
    const int i0 = i & ~127;
    const int jStart = (((i0 * 4) / 5) >> 7) << 7;
    float* p = attn + (size_t)row * S_;
    __half* ph = g_Phat + (size_t)row * S_;
    const int tid = threadIdx.x;

    const int n4 = (S_ - jStart) >> 2;
    float4* p4 = (float4*)(p + jStart);
    const bool val0 = tid < n4;
    const bool val1 = tid + 256 < n4;

    float4 v0 = make_float4(NEG, NEG, NEG, NEG);
    float4 v1 = make_float4(NEG, NEG, NEG, NEG);
    if (val0) v0 = p4[tid];
    if (val1) v1 = p4[tid + 256];

    __shared__ float red[8];

    float m = fmaxf(fmaxf(fmaxf(v0.x, v0.y), fmaxf(v0.z, v0.w)),
                    fmaxf(fmaxf(v1.x, v1.y), fmaxf(v1.z, v1.w)));
    m = warpRedMax(m);
    if ((tid & 31) == 0) red[tid >> 5] = m;
    __syncthreads();
    float bm = red[0];
    #pragma unroll
    for (int k = 1; k < 8; ++k) bm = fmaxf(bm, red[k]);
    __syncthreads();

    v0.x = __expf(v0.x - bm); v0.y = __expf(v0.y - bm);
    v0.z = __expf(v0.z - bm); v0.w = __expf(v0.w - bm);
    v1.x = __expf(v1.x - bm); v1.y = __expf(v1.y - bm);
    v1.z = __expf(v1.z - bm); v1.w = __expf(v1.w - bm);

    float s = 0.0f;
    if (val0) s += (v0.x + v0.y) + (v0.z + v0.w);
    if (val1) s += (v1.x + v1.y) + (v1.z + v1.w);
    s = warpRedSum(s);
    if ((tid & 31) == 0) red[tid >> 5] = s;
    __syncthreads();
    float bs = 0.0f;
    #pragma unroll
    for (int k = 0; k < 8; ++k) bs += red[k];

    const float inv = 1.0f / bs;
    if (val0) {
        v0.x *= inv; v0.y *= inv; v0.z *= inv; v0.w *= inv;
        p4[tid] = v0;
        *(uint2*)&ph[jStart + tid * 4] = cvt4h(v0);
    }
    if (val1) {
        v1.x *= inv; v1.y *= inv; v1.z *= inv; v1.w *= inv;
        p4[tid + 256] = v1;
        *(uint2*)&ph[jStart + (tid + 256) * 4] = cvt4h(v1);
    }
}

// ---------------------------------------------------------------------------
// K3: context = P-hat @ V. 128x128 output per CTA. Warp tile 32x64.
// BOTH operands fp16 in gmem, cp.async double-buffered: no sync convert phase.
// Layout: [P st0][P st1][V st0][V st1], each CH_ELEMS.
// ---------------------------------------------------------------------------
__global__ __launch_bounds__(256, 2) void context_mma_kernel(float* __restrict__ ctx)
{
    const int i0 = blockIdx.x * 128, bh = blockIdx.y;
    const int tid = threadIdx.x;

    extern __shared__ __half sm[];
    const uint32_t smBase = smem_u32(sm);
    const uint32_t pBase = smBase;
    const uint32_t vBase = smBase + 2 * CH_ELEMS * 2;

    const __half* Pb = g_Phat + ((size_t)bh * S_ + i0) * S_;
    const __half* Vt = g_Vt + (size_t)bh * D_ * S_;

    const int lane = tid & 31, warp = tid >> 5;
    const int g = lane >> 2, c = lane & 3;
    const int mb2 = warp & 3;
    const int nb  = warp >> 2;

    float acc[2][8][4];
    #pragma unroll
    for (int s = 0; s < 2; ++s)
        #pragma unroll
        for (int nt = 0; nt < 8; ++nt)
            #pragma unroll
            for (int q = 0; q < 4; ++q) acc[s][nt][q] = 0.0f;

    const uint32_t aRowOff = ((mb2 * 32 + (lane & 15)) * CW + (lane >> 4) * 8) * 2;
    const uint32_t bRowOff = ((nb * 64 + ((lane >> 4) << 3) + (lane & 7)) * CW
                              + ((lane >> 3) & 1) * 8) * 2;

    // cp.async mapping: both P and V chunks are 128 rows x 64 fp16, row stride S_
    const int vn = tid >> 3, vk8 = (tid & 7) << 3;
    const uint32_t cpOff = (uint32_t)(vn * CW + vk8) * 2;

    const int ch0 = (((i0 * 4) / 5) >> 7) * 2;

    auto issue = [&](int ch) {
        const int k0g = ch * 64;
        const uint32_t st = (uint32_t)(ch & 1) * (CH_ELEMS * 2);
        #pragma unroll
        for (int it = 0; it < 4; ++it) {
            int n = vn + it * 32;
            uint32_t d = (uint32_t)(it * 32 * CW) * 2 + cpOff;
            cp_async16(pBase + st + d, &Pb[(size_t)n * S_ + k0g + vk8]);
            cp_async16(vBase + st + d, &Vt[(size_t)n * S_ + k0g + vk8]);
        }
    };

    issue(ch0);
    CP_COMMIT();

    for (int ch = ch0; ch < 32; ++ch) {
        CP_WAIT(0);
        __syncthreads();
        if (ch + 1 < 32) {
            issue(ch + 1);
            CP_COMMIT();
        }
        const uint32_t st = (uint32_t)(ch & 1) * (CH_ELEMS * 2);
        mma_chunk_t<CW, 4>(acc, pBase + st + aRowOff, vBase + st + bRowOff);
    }
    __syncthreads();

    float* stg = (float*)sm;
    #pragma unroll
    for (int s = 0; s < 2; ++s) {
        int r0 = mb2 * 32 + s * 16 + g;
        #pragma unroll
        for (int nt = 0; nt < 8; ++nt) {
            int cc = nb * 64 + nt * 8 + 2 * c;
            *(float2*)&stg[r0 * SGW + cc]       = make_float2(acc[s][nt][0], acc[s][nt][1]);
            *(float2*)&stg[(r0 + 8) * SGW + cc] = make_float2(acc[s][nt][2], acc[s][nt][3]);
        }
    }
    __syncthreads();

    #pragma unroll
    for (int it = 0; it < 16; ++it) {
        int idx = it * 256 + tid;
        int r = idx >> 5, c4 = (idx & 31) << 2;
        *(float4*)&ctx[((size_t)bh * S_ + i0 + r) * D_ + c4] = *(float4*)&stg[r * SGW + c4];
    }
}

// ---------------------------------------------------------------------------
// kernel_launch
// ---------------------------------------------------------------------------
extern "C" void kernel_launch(void* const* d_in, const int* in_sizes, int n_in,
                              void* d_out, int out_size)
{
    const float* Q    = (const float*)d_in[0];
    const float* K    = (const float*)d_in[1];
    const float* V    = (const float*)d_in[2];
    const int*   mask = (const int*)d_in[3];

    float* out  = (float*)d_out;
    float* ctx  = out;
    float* attn = out + (size_t)B_ * H_ * S_ * D_;

    static bool attrs_set = false;
    if (!attrs_set) {
        cudaFuncSetAttribute(scores_mma_kernel, cudaFuncAttributeMaxDynamicSharedMemorySize, SM_BYTES_S);
        cudaFuncSetAttribute(context_mma_kernel, cudaFuncAttributeMaxDynamicSharedMemorySize, SM_BYTES_C);
        attrs_set = true;
    }

    vt_kernel<<<dim3(S_ / 32, D_ / 32, B_ * H_), 256>>>(V);
    qk_prep_kernel<<<8192, 256>>>(Q, K);

    dim3 g1(S_ / 128, S_ / 128, B_ * H_);
    scores_mma_kernel<<<g1, 256, SM_BYTES_S>>>(mask, attn);

    softmax_kernel<<<B_ * H_ * S_, 256>>>(attn);

    dim3 g3(S_ / 128, B_ * H_);
    context_mma_kernel<<<g3, 256, SM_BYTES_C>>>(ctx);

    (void)in_sizes; (void)n_in; (void)out_size;
}